// round 10
// baseline (speedup 1.0000x reference)
#include <cuda_runtime.h>
#include <cuda_fp16.h>

#define Nn 4096
#define Ee 262144
#define FIN 512
#define HID 64
#define NH 8
#define NC 16
#define LALPHA 0.2f

// ---------------- scratch (static __device__, no allocations) ----------------
__device__ unsigned g_bitmap[Nn * Nn / 32];   // 2MB dedup bitmap
__device__ int g_deg[Nn];
__device__ int g_rowptr[Nn + 1];
__device__ int g_rnk[Ee];                     // rank+1 within row, 0 = duplicate
__device__ int g_col[Ee];
__device__ __half g_Ahi[Nn * FIN];                      // fp16 features
__device__ __half g_Whi[FIN * 512], g_Wlo[FIN * 512];   // exact-split Wcat
__device__ __half g_h1h[NH * Nn * HID];       // layer1 h fp16, HEAD-MAJOR [h][n][64]
__device__ __half g_xh[Nn * 512];             // elu(att@h + b) fp16 (4MB), node-major
__device__ float g_s1[NH * Nn];
__device__ float g_s2[NH * Nn];
__device__ float g_h2[Nn * NC];
__device__ float g_t1[Nn];
__device__ float g_t2[Nn];

// ---------------- helpers ----------------
__device__ __forceinline__ float wredsum(float v) {
    #pragma unroll
    for (int o = 16; o; o >>= 1) v += __shfl_xor_sync(0xffffffffu, v, o);
    return v;
}
__device__ __forceinline__ float wredmax(float v) {
    #pragma unroll
    for (int o = 16; o; o >>= 1) v = fmaxf(v, __shfl_xor_sync(0xffffffffu, v, o));
    return v;
}

__device__ __forceinline__ void ldm_x4(unsigned* r, const void* p) {
    unsigned a = (unsigned)__cvta_generic_to_shared(p);
    asm volatile("ldmatrix.sync.aligned.m8n8.x4.shared.b16 {%0,%1,%2,%3}, [%4];"
        : "=r"(r[0]), "=r"(r[1]), "=r"(r[2]), "=r"(r[3]) : "r"(a));
}
__device__ __forceinline__ void ldm_x2t(unsigned* r, const void* p) {
    unsigned a = (unsigned)__cvta_generic_to_shared(p);
    asm volatile("ldmatrix.sync.aligned.m8n8.x2.trans.shared.b16 {%0,%1}, [%2];"
        : "=r"(r[0]), "=r"(r[1]) : "r"(a));
}
__device__ __forceinline__ void mma16816(float* c, const unsigned* a, const unsigned* b) {
    asm volatile("mma.sync.aligned.m16n8k16.row.col.f32.f16.f16.f32 "
        "{%0,%1,%2,%3}, {%4,%5,%6,%7}, {%8,%9}, {%0,%1,%2,%3};"
        : "+f"(c[0]), "+f"(c[1]), "+f"(c[2]), "+f"(c[3])
        : "r"(a[0]), "r"(a[1]), "r"(a[2]), "r"(a[3]), "r"(b[0]), "r"(b[1]));
}

// ---------------- graph build (stream 2) ----------------
__global__ void k_clear_graph() {
    int i = blockIdx.x * blockDim.x + threadIdx.x;
    if (i < Nn * Nn / 128) ((uint4*)g_bitmap)[i] = make_uint4(0, 0, 0, 0);
    if (i < Nn) g_deg[i] = 0;
}

__global__ void k_dedup(const int* __restrict__ el) {   // 4 edges/thread
    int b = 4 * (blockIdx.x * blockDim.x + threadIdx.x);
    if (b >= Ee) return;
    int4 sv = *(const int4*)(el + b);
    int4 tv = *(const int4*)(el + Ee + b);
    int ss[4] = {sv.x, sv.y, sv.z, sv.w};
    int tt[4] = {tv.x, tv.y, tv.z, tv.w};
    unsigned old[4];
    #pragma unroll
    for (int q = 0; q < 4; q++) {
        unsigned idx = ((unsigned)ss[q] << 12) | (unsigned)tt[q];
        old[q] = atomicOr(&g_bitmap[idx >> 5], 1u << (idx & 31));
    }
    int4 rk;
    int* rkp = (int*)&rk;
    #pragma unroll
    for (int q = 0; q < 4; q++) {
        unsigned idx = ((unsigned)ss[q] << 12) | (unsigned)tt[q];
        bool isnew = !(old[q] & (1u << (idx & 31)));
        rkp[q] = isnew ? (atomicAdd(&g_deg[ss[q]], 1) + 1) : 0;
    }
    *(int4*)(g_rnk + b) = rk;
}

__global__ void k_scan() {   // 1 block, 1024 threads, warp-shuffle scan
    __shared__ int warpsum[32];
    int tid = threadIdx.x;
    int lane = tid & 31, wid = tid >> 5;
    int v0 = g_deg[4 * tid + 0];
    int v1 = g_deg[4 * tid + 1];
    int v2 = g_deg[4 * tid + 2];
    int v3 = g_deg[4 * tid + 3];
    int tot = v0 + v1 + v2 + v3;
    int s = tot;
    #pragma unroll
    for (int o = 1; o < 32; o <<= 1) {
        int t = __shfl_up_sync(0xffffffffu, s, o);
        if (lane >= o) s += t;
    }
    if (lane == 31) warpsum[wid] = s;
    __syncthreads();
    if (wid == 0) {
        int ws = warpsum[lane];
        #pragma unroll
        for (int o = 1; o < 32; o <<= 1) {
            int t = __shfl_up_sync(0xffffffffu, ws, o);
            if (lane >= o) ws += t;
        }
        warpsum[lane] = ws;
    }
    __syncthreads();
    int p = (wid ? warpsum[wid - 1] : 0) + s - tot;   // exclusive prefix
    g_rowptr[4 * tid + 0] = p; p += v0;
    g_rowptr[4 * tid + 1] = p; p += v1;
    g_rowptr[4 * tid + 2] = p; p += v2;
    g_rowptr[4 * tid + 3] = p; p += v3;
    if (tid == 1023) g_rowptr[Nn] = warpsum[31];
}

__global__ void k_scatter(const int* __restrict__ el) {  // atomic-free
    int b = 4 * (blockIdx.x * blockDim.x + threadIdx.x);
    if (b >= Ee) return;
    int4 sv = *(const int4*)(el + b);
    int4 tv = *(const int4*)(el + Ee + b);
    int4 rv = *(const int4*)(g_rnk + b);
    int ss[4] = {sv.x, sv.y, sv.z, sv.w};
    int tt[4] = {tv.x, tv.y, tv.z, tv.w};
    int rr[4] = {rv.x, rv.y, rv.z, rv.w};
    #pragma unroll
    for (int q = 0; q < 4; q++)
        if (rr[q]) g_col[g_rowptr[ss[q]] + rr[q] - 1] = tt[q];
}

// ---------------- fp32 -> fp16 A, exact (hi,lo) split of Wcat ----------------
__global__ void k_tohalf(const float* __restrict__ A, const float* __restrict__ Wh) {
    int i = blockIdx.x * blockDim.x + threadIdx.x;   // float4 group
    const int NA4 = Nn * FIN / 4;
    if (i < NA4) {
        float4 v = ((const float4*)A)[i];
        ((__half2*)g_Ahi)[2 * i] = __floats2half2_rn(v.x, v.y);
        ((__half2*)g_Ahi)[2 * i + 1] = __floats2half2_rn(v.z, v.w);
    } else if (i < NA4 + FIN * 512 / 4) {
        int j = (i - NA4) * 4;           // element index in Wcat [FIN][512]
        int k = j >> 9, c = j & 511;
        int hh = c >> 6, jj = c & 63;
        float4 v = *(const float4*)(Wh + hh * (FIN * HID) + k * HID + jj);
        __half h0 = __float2half_rn(v.x), h1 = __float2half_rn(v.y);
        __half h2 = __float2half_rn(v.z), h3 = __float2half_rn(v.w);
        __half2* dst_hi = (__half2*)(g_Whi + k * 512 + c);
        __half2* dst_lo = (__half2*)(g_Wlo + k * 512 + c);
        dst_hi[0] = __halves2half2(h0, h1);
        dst_hi[1] = __halves2half2(h2, h3);
        dst_lo[0] = __halves2half2(
            __float2half_rn(v.x - __half2float(h0)), __float2half_rn(v.y - __half2float(h1)));
        dst_lo[1] = __halves2half2(
            __float2half_rn(v.z - __half2float(h2)), __float2half_rn(v.w - __half2float(h3)));
    }
}

// ---- GEMM1 (128x128, 2-term split) with FUSED per-node score epilogue ------
#define BM 128
#define BN 128
#define BK 32
#define LDA 40
#define LDB 136

__global__ void __launch_bounds__(256) k_gemm1_mma(const float* __restrict__ a_heads) {
    __shared__ __half As[BM][LDA];
    __shared__ __half Bs_hi[BK][LDB], Bs_lo[BK][LDB];
    __shared__ float sred[128][2][2][2];   // [row][head-local][p1/p2][wn parity]
    int tid = threadIdx.x;
    int wid = tid >> 5, lane = tid & 31;
    int wm = wid & 1, wn = wid >> 1;          // warp tile: 64x32
    int row0 = blockIdx.y * BM, col0 = blockIdx.x * BN;

    int arow = tid >> 1, acol = (tid & 1) * 16;   // 16 halves of A per thread
    int bkrow = tid >> 3, bn = (tid & 7) * 16;    // 16 halves of B per thread
    const __half* aph = g_Ahi + (row0 + arow) * FIN + acol;
    const __half* bph = g_Whi + bkrow * 512 + col0 + bn;
    const __half* bpl = g_Wlo + bkrow * 512 + col0 + bn;

    uint4 rah[2], rbh[2], rbl[2];
    rah[0] = *(const uint4*)(aph);     rah[1] = *(const uint4*)(aph + 8);
    rbh[0] = *(const uint4*)(bph);     rbh[1] = *(const uint4*)(bph + 8);
    rbl[0] = *(const uint4*)(bpl);     rbl[1] = *(const uint4*)(bpl + 8);

    float acc[4][4][4];
    #pragma unroll
    for (int mi = 0; mi < 4; mi++)
        #pragma unroll
        for (int ni = 0; ni < 4; ni++)
            #pragma unroll
            for (int q = 0; q < 4; q++) acc[mi][ni][q] = 0.f;

    for (int k0 = 0; k0 < FIN; k0 += BK) {
        *(uint4*)&As[arow][acol] = rah[0];
        *(uint4*)&As[arow][acol + 8] = rah[1];
        *(uint4*)&Bs_hi[bkrow][bn] = rbh[0];
        *(uint4*)&Bs_hi[bkrow][bn + 8] = rbh[1];
        *(uint4*)&Bs_lo[bkrow][bn] = rbl[0];
        *(uint4*)&Bs_lo[bkrow][bn + 8] = rbl[1];
        __syncthreads();
        if (k0 + BK < FIN) {
            rah[0] = *(const uint4*)(aph + k0 + BK);
            rah[1] = *(const uint4*)(aph + k0 + BK + 8);
            rbh[0] = *(const uint4*)(bph + (k0 + BK) * 512);
            rbh[1] = *(const uint4*)(bph + (k0 + BK) * 512 + 8);
            rbl[0] = *(const uint4*)(bpl + (k0 + BK) * 512);
            rbl[1] = *(const uint4*)(bpl + (k0 + BK) * 512 + 8);
        }
        #pragma unroll
        for (int ks = 0; ks < BK; ks += 16) {
            unsigned af[4][4], bfh[4][2], bfl[4][2];
            #pragma unroll
            for (int mi = 0; mi < 4; mi++) {
                int r = wm * 64 + mi * 16 + (lane & 15);
                int c = ks + (lane >> 4) * 8;
                ldm_x4(af[mi], &As[r][c]);
            }
            #pragma unroll
            for (int ni = 0; ni < 4; ni++) {
                int kr = ks + (lane & 15);
                int nc = wn * 32 + ni * 8;
                ldm_x2t(bfh[ni], &Bs_hi[kr][nc]);
                ldm_x2t(bfl[ni], &Bs_lo[kr][nc]);
            }
            #pragma unroll
            for (int mi = 0; mi < 4; mi++)
                #pragma unroll
                for (int ni = 0; ni < 4; ni++) {
                    mma16816(acc[mi][ni], af[mi], bfh[ni]);
                    mma16816(acc[mi][ni], af[mi], bfl[ni]);
                }
        }
        __syncthreads();
    }
    // h1h stores — HEAD-MAJOR: g_h1h[head][node][64]
    #pragma unroll
    for (int mi = 0; mi < 4; mi++)
        #pragma unroll
        for (int ni = 0; ni < 4; ni++) {
            int r = row0 + wm * 64 + mi * 16 + (lane >> 2);
            int c = col0 + wn * 32 + ni * 8 + (lane & 3) * 2;
            int head = c >> 6, cl = c & 63;
            __half* base = g_h1h + ((size_t)head * Nn) * HID + cl;
            *(__half2*)(base + r * HID) =
                __floats2half2_rn(acc[mi][ni][0], acc[mi][ni][1]);
            *(__half2*)(base + (r + 8) * HID) =
                __floats2half2_rn(acc[mi][ni][2], acc[mi][ni][3]);
        }
    // fused per-node score epilogue
    {
        int hl = wn >> 1;
        int par = wn & 1;
        const float* av = a_heads + (2 * blockIdx.x + hl) * 128;
        float a1v[8], a2v[8];
        #pragma unroll
        for (int ni = 0; ni < 4; ni++) {
            int cl = par * 32 + ni * 8 + (lane & 3) * 2;  // head-local col (0..63)
            a1v[2 * ni] = av[cl];       a1v[2 * ni + 1] = av[cl + 1];
            a2v[2 * ni] = av[64 + cl];  a2v[2 * ni + 1] = av[65 + cl];
        }
        #pragma unroll
        for (int mi = 0; mi < 4; mi++) {
            float p1a = 0.f, p2a = 0.f, p1b = 0.f, p2b = 0.f;
            #pragma unroll
            for (int ni = 0; ni < 4; ni++) {
                p1a += acc[mi][ni][0] * a1v[2 * ni] + acc[mi][ni][1] * a1v[2 * ni + 1];
                p2a += acc[mi][ni][0] * a2v[2 * ni] + acc[mi][ni][1] * a2v[2 * ni + 1];
                p1b += acc[mi][ni][2] * a1v[2 * ni] + acc[mi][ni][3] * a1v[2 * ni + 1];
                p2b += acc[mi][ni][2] * a2v[2 * ni] + acc[mi][ni][3] * a2v[2 * ni + 1];
            }
            #pragma unroll
            for (int o = 1; o <= 2; o <<= 1) {
                p1a += __shfl_xor_sync(0xffffffffu, p1a, o);
                p2a += __shfl_xor_sync(0xffffffffu, p2a, o);
                p1b += __shfl_xor_sync(0xffffffffu, p1b, o);
                p2b += __shfl_xor_sync(0xffffffffu, p2b, o);
            }
            if ((lane & 3) == 0) {
                int r = wm * 64 + mi * 16 + (lane >> 2);
                sred[r][hl][0][par] = p1a;
                sred[r][hl][1][par] = p2a;
                sred[r + 8][hl][0][par] = p1b;
                sred[r + 8][hl][1][par] = p2b;
            }
        }
        __syncthreads();
        for (int o = tid; o < 512; o += 256) {
            int r = o & 127, hh = (o >> 7) & 1, p = (o >> 8) & 1;
            float val = sred[r][hh][p][0] + sred[r][hh][p][1];
            float* dst = p ? g_s2 : g_s1;
            dst[(2 * blockIdx.x + hh) * Nn + row0 + r] = val;
        }
    }
}

// ---------------- layer-1 aggregation: block = (8 nodes, 1 head) ----------
// grid (Nn/8, NH); head-specialized so co-resident warps share one 512KB region.
__global__ void __launch_bounds__(256) k_agg1(const float* __restrict__ b_heads) {
    __shared__ float wbuf[8][132];
    __shared__ int   cbuf[8][132];
    int w = threadIdx.x >> 5, lane = threadIdx.x & 31;
    int i = blockIdx.x * 8 + w;
    int h = blockIdx.y;
    int p0 = g_rowptr[i], p1 = g_rowptr[i + 1];
    int deg = p1 - p0;
    float o0 = 0.f, o1 = 0.f;
    const __half2* hb = ((const __half2*)g_h1h) + (size_t)h * Nn * 32 + lane;
    if (deg > 0 && deg <= 128) {
        float s1i = g_s1[h * Nn + i];
        const float* s2p = g_s2 + h * Nn;
        float m = -1e30f;
        for (int j = lane; j < deg; j += 32) {
            int t = g_col[p0 + j];
            cbuf[w][j] = t;
            float e = s1i + s2p[t];
            e = e > 0.f ? e : LALPHA * e;
            wbuf[w][j] = e;
            m = fmaxf(m, e);
        }
        m = wredmax(m);
        float ss = 0.f;
        for (int j = lane; j < deg; j += 32) {
            float wv = expf(wbuf[w][j] - m);
            wbuf[w][j] = wv;
            ss += wv;
        }
        ss = wredsum(ss);
        __syncwarp();
        float inv = 1.f / ss;
        float a0 = 0.f, a1 = 0.f;
        #pragma unroll 8
        for (int j = 0; j < deg; j++) {
            int t = cbuf[w][j];
            float wv = wbuf[w][j];
            float2 v = __half22float2(hb[t * 32]);
            a0 = fmaf(wv, v.x, a0);
            a1 = fmaf(wv, v.y, a1);
        }
        o0 = a0 * inv; o1 = a1 * inv;
    } else if (deg > 128) {   // rare fallback
        float s1i = g_s1[h * Nn + i];
        const float* s2p = g_s2 + h * Nn;
        float m = -1e30f;
        for (int p = p0 + lane; p < p1; p += 32) {
            float e = s1i + s2p[g_col[p]];
            e = e > 0.f ? e : LALPHA * e;
            m = fmaxf(m, e);
        }
        m = wredmax(m);
        float ss = 0.f;
        for (int p = p0 + lane; p < p1; p += 32) {
            float e = s1i + s2p[g_col[p]];
            e = e > 0.f ? e : LALPHA * e;
            ss += expf(e - m);
        }
        ss = wredsum(ss);
        float inv = 1.f / ss;
        float a0 = 0.f, a1 = 0.f;
        for (int p = p0; p < p1; p++) {
            int t = g_col[p];
            float e = s1i + s2p[t];
            e = e > 0.f ? e : LALPHA * e;
            float wv = expf(e - m) * inv;
            float2 v = __half22float2(hb[t * 32]);
            a0 = fmaf(wv, v.x, a0);
            a1 = fmaf(wv, v.y, a1);
        }
        o0 = a0; o1 = a1;
    }
    int c0 = h * HID + 2 * lane;
    o0 += b_heads[c0];
    o1 += b_heads[c0 + 1];
    o0 = o0 > 0.f ? o0 : expm1f(o0);   // elu
    o1 = o1 > 0.f ? o1 : expm1f(o1);
    *(__half2*)(g_xh + i * 512 + c0) = __floats2half2_rn(o0, o1);
}

// ---------------- GEMM2 (fp16 x) + fused layer-2 scores ----------------
#define LDW 516
__global__ void __launch_bounds__(256) k_gemm2(const float* __restrict__ Wout,
                                               const float* __restrict__ a_out) {
    __shared__ float WsT[NC][LDW];   // transposed, padded
    int tid = threadIdx.x;
    for (int j = tid; j < 512 * NC; j += 256) WsT[j & 15][j >> 4] = Wout[j];
    __syncthreads();
    int col = tid & 15, rs = tid >> 4;
    int row = blockIdx.x * 16 + rs;
    const __half2* xp2 = (const __half2*)(g_xh + row * 512);
    const float4* wp4 = (const float4*)WsT[col];
    float a0 = 0.f, a1 = 0.f, a2 = 0.f, a3 = 0.f;
    #pragma unroll 8
    for (int k = 0; k < 128; k++) {
        float4 wv = wp4[k];
        float2 xa = __half22float2(xp2[2 * k]);
        float2 xb = __half22float2(xp2[2 * k + 1]);
        a0 = fmaf(xa.x, wv.x, a0);
        a1 = fmaf(xa.y, wv.y, a1);
        a2 = fmaf(xb.x, wv.z, a2);
        a3 = fmaf(xb.y, wv.w, a3);
    }
    float v = (a0 + a1) + (a2 + a3);
    g_h2[row * NC + col] = v;
    // fused scores2
    float q1 = v * a_out[col];
    float q2 = v * a_out[16 + col];
    #pragma unroll
    for (int o = 8; o; o >>= 1) {
        q1 += __shfl_xor_sync(0xffffffffu, q1, o);
        q2 += __shfl_xor_sync(0xffffffffu, q2, o);
    }
    if (col == 0) { g_t1[row] = q1; g_t2[row] = q2; }
}

// ---------------- layer-2 aggregation + log_softmax ----------------
__global__ void __launch_bounds__(256) k_agg2(const float* __restrict__ b_out,
                                              float* __restrict__ out) {
    __shared__ float wbuf[8][132];
    __shared__ int   cbuf[8][132];
    int wid = threadIdx.x >> 5, lane = threadIdx.x & 31;
    int i = blockIdx.x * 8 + wid;
    int p0 = g_rowptr[i], p1 = g_rowptr[i + 1];
    int deg = p1 - p0;
    float logit = 0.f;
    if (deg > 0 && deg <= 128) {
        float t1i = g_t1[i];
        float m = -1e30f;
        for (int j = lane; j < deg; j += 32) {
            int t = g_col[p0 + j];
            cbuf[wid][j] = t;
            float e = t1i + g_t2[t];
            e = e > 0.f ? e : LALPHA * e;
            wbuf[wid][j] = e;
            m = fmaxf(m, e);
        }
        m = wredmax(m);
        float ss = 0.f;
        for (int j = lane; j < deg; j += 32) {
            float w = expf(wbuf[wid][j] - m);
            wbuf[wid][j] = w;
            ss += w;
        }
        ss = wredsum(ss);
        __syncwarp();
        float inv = 1.f / ss;
        float acc = 0.f;
        #pragma unroll 4
        for (int j = 0; j < deg; j++) {
            int t = cbuf[wid][j];
            float w = wbuf[wid][j];
            if (lane < 16) acc = fmaf(w, g_h2[t * NC + lane], acc);
        }
        if (lane < 16) logit = acc * inv + b_out[lane];
    } else if (deg > 128) {
        float t1i = g_t1[i];
        float m = -1e30f;
        for (int p = p0 + lane; p < p1; p += 32) {
            float e = t1i + g_t2[g_col[p]];
            e = e > 0.f ? e : LALPHA * e;
            m = fmaxf(m, e);
        }
        m = wredmax(m);
        float ss = 0.f;
        for (int p = p0 + lane; p < p1; p += 32) {
            float e = t1i + g_t2[g_col[p]];
            e = e > 0.f ? e : LALPHA * e;
            ss += expf(e - m);
        }
        ss = wredsum(ss);
        float inv = 1.f / ss;
        float acc = 0.f;
        for (int p = p0; p < p1; p++) {
            int t = g_col[p];
            float e = t1i + g_t2[t];
            e = e > 0.f ? e : LALPHA * e;
            float w = expf(e - m) * inv;
            if (lane < 16) acc = fmaf(w, g_h2[t * NC + lane], acc);
        }
        if (lane < 16) logit = acc + b_out[lane];
    } else {
        if (lane < 16) logit = b_out[lane];   // deg==0: unreachable on this dataset
    }
    // log_softmax over 16 classes
    float lm = (lane < 16) ? logit : -1e30f;
    #pragma unroll
    for (int o = 8; o; o >>= 1) lm = fmaxf(lm, __shfl_xor_sync(0xffffffffu, lm, o));
    float es = (lane < 16) ? expf(logit - lm) : 0.f;
    #pragma unroll
    for (int o = 8; o; o >>= 1) es += __shfl_xor_sync(0xffffffffu, es, o);
    if (lane < 16) out[i * NC + lane] = logit - lm - logf(es);
}

// ---------------- side stream (created once, host resources only) ----------
struct SideStream {
    cudaStream_t s2;
    cudaEvent_t eFork, eJoin;
    SideStream() {
        cudaStreamCreateWithFlags(&s2, cudaStreamNonBlocking);
        cudaEventCreateWithFlags(&eFork, cudaEventDisableTiming);
        cudaEventCreateWithFlags(&eJoin, cudaEventDisableTiming);
    }
};
static SideStream g_ss;

// ---------------- launch ----------------
extern "C" void kernel_launch(void* const* d_in, const int* in_sizes, int n_in,
                              void* d_out, int out_size) {
    const float* features    = (const float*)d_in[0];
    const int* el            = (const int*)d_in[1];
    const float* W_heads     = (const float*)d_in[2];
    const float* a_heads     = (const float*)d_in[3];
    const float* b_heads     = (const float*)d_in[4];
    const float* W_out       = (const float*)d_in[5];
    const float* a_out       = (const float*)d_in[6];
    const float* b_out       = (const float*)d_in[7];
    float* out = (float*)d_out;

    // fork: graph-build chain on side stream
    cudaEventRecord(g_ss.eFork, 0);
    cudaStreamWaitEvent(g_ss.s2, g_ss.eFork, 0);
    k_clear_graph<<<(Nn * Nn / 128 + 255) / 256, 256, 0, g_ss.s2>>>();
    k_dedup<<<Ee / 1024, 256, 0, g_ss.s2>>>(el);
    k_scan<<<1, 1024, 0, g_ss.s2>>>();
    k_scatter<<<Ee / 1024, 256, 0, g_ss.s2>>>(el);
    cudaEventRecord(g_ss.eJoin, g_ss.s2);

    // main chain: compute
    k_tohalf<<<(Nn * FIN / 4 + FIN * 512 / 4 + 255) / 256, 256>>>(features, W_heads);
    k_gemm1_mma<<<dim3(4, 32), 256>>>(a_heads);

    // join, then the dependent tail
    cudaStreamWaitEvent(0, g_ss.eJoin, 0);
    k_agg1<<<dim3(Nn / 8, NH), 256>>>(b_heads);
    k_gemm2<<<Nn / 16, 256>>>(W_out, a_out);
    k_agg2<<<Nn / 8, 256>>>(b_out, out);
}

// round 11
// speedup vs baseline: 1.0758x; 1.0758x over previous
#include <cuda_runtime.h>
#include <cuda_fp16.h>

#define Nn 4096
#define Ee 262144
#define FIN 512
#define HID 64
#define NH 8
#define NC 16
#define LALPHA 0.2f

// ---------------- scratch (static __device__, no allocations) ----------------
__device__ unsigned g_bitmap[Nn * Nn / 32];   // 2MB dedup bitmap
__device__ int g_deg[Nn];
__device__ int g_rowptr[Nn + 1];
__device__ int g_rnk[Ee];                     // rank+1 within row, 0 = duplicate
__device__ int g_col[Ee];
__device__ __half g_Ahi[Nn * FIN];                      // fp16 features
__device__ __half g_Whi[FIN * 512], g_Wlo[FIN * 512];   // exact-split Wcat
__device__ __half g_h1h[NH * Nn * HID];       // layer1 h fp16, HEAD-MAJOR [h][n][64]
__device__ __half g_xh[Nn * 512];             // elu(att@h + b) fp16 (4MB), node-major
__device__ float g_s1[NH * Nn];
__device__ float g_s2[NH * Nn];
__device__ __half g_h2h[Nn * NC];             // layer2 h fp16 (128KB)
__device__ float g_t1[Nn];
__device__ float g_t2[Nn];

// ---------------- helpers ----------------
__device__ __forceinline__ float wredsum(float v) {
    #pragma unroll
    for (int o = 16; o; o >>= 1) v += __shfl_xor_sync(0xffffffffu, v, o);
    return v;
}
__device__ __forceinline__ float wredmax(float v) {
    #pragma unroll
    for (int o = 16; o; o >>= 1) v = fmaxf(v, __shfl_xor_sync(0xffffffffu, v, o));
    return v;
}

__device__ __forceinline__ void ldm_x4(unsigned* r, const void* p) {
    unsigned a = (unsigned)__cvta_generic_to_shared(p);
    asm volatile("ldmatrix.sync.aligned.m8n8.x4.shared.b16 {%0,%1,%2,%3}, [%4];"
        : "=r"(r[0]), "=r"(r[1]), "=r"(r[2]), "=r"(r[3]) : "r"(a));
}
__device__ __forceinline__ void ldm_x2t(unsigned* r, const void* p) {
    unsigned a = (unsigned)__cvta_generic_to_shared(p);
    asm volatile("ldmatrix.sync.aligned.m8n8.x2.trans.shared.b16 {%0,%1}, [%2];"
        : "=r"(r[0]), "=r"(r[1]) : "r"(a));
}
__device__ __forceinline__ void mma16816(float* c, const unsigned* a, const unsigned* b) {
    asm volatile("mma.sync.aligned.m16n8k16.row.col.f32.f16.f16.f32 "
        "{%0,%1,%2,%3}, {%4,%5,%6,%7}, {%8,%9}, {%0,%1,%2,%3};"
        : "+f"(c[0]), "+f"(c[1]), "+f"(c[2]), "+f"(c[3])
        : "r"(a[0]), "r"(a[1]), "r"(a[2]), "r"(a[3]), "r"(b[0]), "r"(b[1]));
}

// ---------------- graph build (stream 2) ----------------
__global__ void k_clear_graph() {
    int i = blockIdx.x * blockDim.x + threadIdx.x;
    if (i < Nn * Nn / 128) ((uint4*)g_bitmap)[i] = make_uint4(0, 0, 0, 0);
    if (i < Nn) g_deg[i] = 0;
}

__global__ void k_dedup(const int* __restrict__ el) {   // 4 edges/thread
    int b = 4 * (blockIdx.x * blockDim.x + threadIdx.x);
    if (b >= Ee) return;
    int4 sv = *(const int4*)(el + b);
    int4 tv = *(const int4*)(el + Ee + b);
    int ss[4] = {sv.x, sv.y, sv.z, sv.w};
    int tt[4] = {tv.x, tv.y, tv.z, tv.w};
    unsigned old[4];
    #pragma unroll
    for (int q = 0; q < 4; q++) {
        unsigned idx = ((unsigned)ss[q] << 12) | (unsigned)tt[q];
        old[q] = atomicOr(&g_bitmap[idx >> 5], 1u << (idx & 31));
    }
    int4 rk;
    int* rkp = (int*)&rk;
    #pragma unroll
    for (int q = 0; q < 4; q++) {
        unsigned idx = ((unsigned)ss[q] << 12) | (unsigned)tt[q];
        bool isnew = !(old[q] & (1u << (idx & 31)));
        rkp[q] = isnew ? (atomicAdd(&g_deg[ss[q]], 1) + 1) : 0;
    }
    *(int4*)(g_rnk + b) = rk;
}

__global__ void k_scan() {   // 1 block, 1024 threads, warp-shuffle scan
    __shared__ int warpsum[32];
    int tid = threadIdx.x;
    int lane = tid & 31, wid = tid >> 5;
    int v0 = g_deg[4 * tid + 0];
    int v1 = g_deg[4 * tid + 1];
    int v2 = g_deg[4 * tid + 2];
    int v3 = g_deg[4 * tid + 3];
    int tot = v0 + v1 + v2 + v3;
    int s = tot;
    #pragma unroll
    for (int o = 1; o < 32; o <<= 1) {
        int t = __shfl_up_sync(0xffffffffu, s, o);
        if (lane >= o) s += t;
    }
    if (lane == 31) warpsum[wid] = s;
    __syncthreads();
    if (wid == 0) {
        int ws = warpsum[lane];
        #pragma unroll
        for (int o = 1; o < 32; o <<= 1) {
            int t = __shfl_up_sync(0xffffffffu, ws, o);
            if (lane >= o) ws += t;
        }
        warpsum[lane] = ws;
    }
    __syncthreads();
    int p = (wid ? warpsum[wid - 1] : 0) + s - tot;   // exclusive prefix
    g_rowptr[4 * tid + 0] = p; p += v0;
    g_rowptr[4 * tid + 1] = p; p += v1;
    g_rowptr[4 * tid + 2] = p; p += v2;
    g_rowptr[4 * tid + 3] = p; p += v3;
    if (tid == 1023) g_rowptr[Nn] = warpsum[31];
}

__global__ void k_scatter(const int* __restrict__ el) {  // atomic-free
    int b = 4 * (blockIdx.x * blockDim.x + threadIdx.x);
    if (b >= Ee) return;
    int4 sv = *(const int4*)(el + b);
    int4 tv = *(const int4*)(el + Ee + b);
    int4 rv = *(const int4*)(g_rnk + b);
    int ss[4] = {sv.x, sv.y, sv.z, sv.w};
    int tt[4] = {tv.x, tv.y, tv.z, tv.w};
    int rr[4] = {rv.x, rv.y, rv.z, rv.w};
    #pragma unroll
    for (int q = 0; q < 4; q++)
        if (rr[q]) g_col[g_rowptr[ss[q]] + rr[q] - 1] = tt[q];
}

// ---------------- fp32 -> fp16 A, exact (hi,lo) split of Wcat ----------------
__global__ void k_tohalf(const float* __restrict__ A, const float* __restrict__ Wh) {
    int i = blockIdx.x * blockDim.x + threadIdx.x;   // float4 group
    const int NA4 = Nn * FIN / 4;
    if (i < NA4) {
        float4 v = ((const float4*)A)[i];
        ((__half2*)g_Ahi)[2 * i] = __floats2half2_rn(v.x, v.y);
        ((__half2*)g_Ahi)[2 * i + 1] = __floats2half2_rn(v.z, v.w);
    } else if (i < NA4 + FIN * 512 / 4) {
        int j = (i - NA4) * 4;           // element index in Wcat [FIN][512]
        int k = j >> 9, c = j & 511;
        int hh = c >> 6, jj = c & 63;
        float4 v = *(const float4*)(Wh + hh * (FIN * HID) + k * HID + jj);
        __half h0 = __float2half_rn(v.x), h1 = __float2half_rn(v.y);
        __half h2 = __float2half_rn(v.z), h3 = __float2half_rn(v.w);
        __half2* dst_hi = (__half2*)(g_Whi + k * 512 + c);
        __half2* dst_lo = (__half2*)(g_Wlo + k * 512 + c);
        dst_hi[0] = __halves2half2(h0, h1);
        dst_hi[1] = __halves2half2(h2, h3);
        dst_lo[0] = __halves2half2(
            __float2half_rn(v.x - __half2float(h0)), __float2half_rn(v.y - __half2float(h1)));
        dst_lo[1] = __halves2half2(
            __float2half_rn(v.z - __half2float(h2)), __float2half_rn(v.w - __half2float(h3)));
    }
}

// ---- GEMM1 (128x128, 2-term split) with FUSED per-node score epilogue ------
#define BM 128
#define BN 128
#define BK 32
#define LDA 40
#define LDB 136

__global__ void __launch_bounds__(256) k_gemm1_mma(const float* __restrict__ a_heads) {
    __shared__ __half As[BM][LDA];
    __shared__ __half Bs_hi[BK][LDB], Bs_lo[BK][LDB];
    __shared__ float sred[128][2][2][2];   // [row][head-local][p1/p2][wn parity]
    int tid = threadIdx.x;
    int wid = tid >> 5, lane = tid & 31;
    int wm = wid & 1, wn = wid >> 1;          // warp tile: 64x32
    int row0 = blockIdx.y * BM, col0 = blockIdx.x * BN;

    int arow = tid >> 1, acol = (tid & 1) * 16;   // 16 halves of A per thread
    int bkrow = tid >> 3, bn = (tid & 7) * 16;    // 16 halves of B per thread
    const __half* aph = g_Ahi + (row0 + arow) * FIN + acol;
    const __half* bph = g_Whi + bkrow * 512 + col0 + bn;
    const __half* bpl = g_Wlo + bkrow * 512 + col0 + bn;

    uint4 rah[2], rbh[2], rbl[2];
    rah[0] = *(const uint4*)(aph);     rah[1] = *(const uint4*)(aph + 8);
    rbh[0] = *(const uint4*)(bph);     rbh[1] = *(const uint4*)(bph + 8);
    rbl[0] = *(const uint4*)(bpl);     rbl[1] = *(const uint4*)(bpl + 8);

    float acc[4][4][4];
    #pragma unroll
    for (int mi = 0; mi < 4; mi++)
        #pragma unroll
        for (int ni = 0; ni < 4; ni++)
            #pragma unroll
            for (int q = 0; q < 4; q++) acc[mi][ni][q] = 0.f;

    for (int k0 = 0; k0 < FIN; k0 += BK) {
        *(uint4*)&As[arow][acol] = rah[0];
        *(uint4*)&As[arow][acol + 8] = rah[1];
        *(uint4*)&Bs_hi[bkrow][bn] = rbh[0];
        *(uint4*)&Bs_hi[bkrow][bn + 8] = rbh[1];
        *(uint4*)&Bs_lo[bkrow][bn] = rbl[0];
        *(uint4*)&Bs_lo[bkrow][bn + 8] = rbl[1];
        __syncthreads();
        if (k0 + BK < FIN) {
            rah[0] = *(const uint4*)(aph + k0 + BK);
            rah[1] = *(const uint4*)(aph + k0 + BK + 8);
            rbh[0] = *(const uint4*)(bph + (k0 + BK) * 512);
            rbh[1] = *(const uint4*)(bph + (k0 + BK) * 512 + 8);
            rbl[0] = *(const uint4*)(bpl + (k0 + BK) * 512);
            rbl[1] = *(const uint4*)(bpl + (k0 + BK) * 512 + 8);
        }
        #pragma unroll
        for (int ks = 0; ks < BK; ks += 16) {
            unsigned af[4][4], bfh[4][2], bfl[4][2];
            #pragma unroll
            for (int mi = 0; mi < 4; mi++) {
                int r = wm * 64 + mi * 16 + (lane & 15);
                int c = ks + (lane >> 4) * 8;
                ldm_x4(af[mi], &As[r][c]);
            }
            #pragma unroll
            for (int ni = 0; ni < 4; ni++) {
                int kr = ks + (lane & 15);
                int nc = wn * 32 + ni * 8;
                ldm_x2t(bfh[ni], &Bs_hi[kr][nc]);
                ldm_x2t(bfl[ni], &Bs_lo[kr][nc]);
            }
            #pragma unroll
            for (int mi = 0; mi < 4; mi++)
                #pragma unroll
                for (int ni = 0; ni < 4; ni++) {
                    mma16816(acc[mi][ni], af[mi], bfh[ni]);
                    mma16816(acc[mi][ni], af[mi], bfl[ni]);
                }
        }
        __syncthreads();
    }
    // h1h stores — HEAD-MAJOR: g_h1h[head][node][64]
    #pragma unroll
    for (int mi = 0; mi < 4; mi++)
        #pragma unroll
        for (int ni = 0; ni < 4; ni++) {
            int r = row0 + wm * 64 + mi * 16 + (lane >> 2);
            int c = col0 + wn * 32 + ni * 8 + (lane & 3) * 2;
            int head = c >> 6, cl = c & 63;
            __half* base = g_h1h + ((size_t)head * Nn) * HID + cl;
            *(__half2*)(base + r * HID) =
                __floats2half2_rn(acc[mi][ni][0], acc[mi][ni][1]);
            *(__half2*)(base + (r + 8) * HID) =
                __floats2half2_rn(acc[mi][ni][2], acc[mi][ni][3]);
        }
    // fused per-node score epilogue
    {
        int hl = wn >> 1;
        int par = wn & 1;
        const float* av = a_heads + (2 * blockIdx.x + hl) * 128;
        float a1v[8], a2v[8];
        #pragma unroll
        for (int ni = 0; ni < 4; ni++) {
            int cl = par * 32 + ni * 8 + (lane & 3) * 2;  // head-local col (0..63)
            a1v[2 * ni] = av[cl];       a1v[2 * ni + 1] = av[cl + 1];
            a2v[2 * ni] = av[64 + cl];  a2v[2 * ni + 1] = av[65 + cl];
        }
        #pragma unroll
        for (int mi = 0; mi < 4; mi++) {
            float p1a = 0.f, p2a = 0.f, p1b = 0.f, p2b = 0.f;
            #pragma unroll
            for (int ni = 0; ni < 4; ni++) {
                p1a += acc[mi][ni][0] * a1v[2 * ni] + acc[mi][ni][1] * a1v[2 * ni + 1];
                p2a += acc[mi][ni][0] * a2v[2 * ni] + acc[mi][ni][1] * a2v[2 * ni + 1];
                p1b += acc[mi][ni][2] * a1v[2 * ni] + acc[mi][ni][3] * a1v[2 * ni + 1];
                p2b += acc[mi][ni][2] * a2v[2 * ni] + acc[mi][ni][3] * a2v[2 * ni + 1];
            }
            #pragma unroll
            for (int o = 1; o <= 2; o <<= 1) {
                p1a += __shfl_xor_sync(0xffffffffu, p1a, o);
                p2a += __shfl_xor_sync(0xffffffffu, p2a, o);
                p1b += __shfl_xor_sync(0xffffffffu, p1b, o);
                p2b += __shfl_xor_sync(0xffffffffu, p2b, o);
            }
            if ((lane & 3) == 0) {
                int r = wm * 64 + mi * 16 + (lane >> 2);
                sred[r][hl][0][par] = p1a;
                sred[r][hl][1][par] = p2a;
                sred[r + 8][hl][0][par] = p1b;
                sred[r + 8][hl][1][par] = p2b;
            }
        }
        __syncthreads();
        for (int o = tid; o < 512; o += 256) {
            int r = o & 127, hh = (o >> 7) & 1, p = (o >> 8) & 1;
            float val = sred[r][hh][p][0] + sred[r][hh][p][1];
            float* dst = p ? g_s2 : g_s1;
            dst[(2 * blockIdx.x + hh) * Nn + row0 + r] = val;
        }
    }
}

// ---------------- layer-1 aggregation: block = (8 nodes, 1 head) ----------
__global__ void __launch_bounds__(256) k_agg1(const float* __restrict__ b_heads) {
    __shared__ float wbuf[8][132];
    __shared__ int   cbuf[8][132];
    int w = threadIdx.x >> 5, lane = threadIdx.x & 31;
    int i = blockIdx.x * 8 + w;
    int h = blockIdx.y;
    int p0 = g_rowptr[i], p1 = g_rowptr[i + 1];
    int deg = p1 - p0;
    float o0 = 0.f, o1 = 0.f;
    const __half2* hb = ((const __half2*)g_h1h) + (size_t)h * Nn * 32 + lane;
    if (deg > 0 && deg <= 128) {
        float s1i = g_s1[h * Nn + i];
        const float* s2p = g_s2 + h * Nn;
        float m = -1e30f;
        for (int j = lane; j < deg; j += 32) {
            int t = g_col[p0 + j];
            cbuf[w][j] = t;
            float e = s1i + s2p[t];
            e = e > 0.f ? e : LALPHA * e;
            wbuf[w][j] = e;
            m = fmaxf(m, e);
        }
        m = wredmax(m);
        float ss = 0.f;
        for (int j = lane; j < deg; j += 32) {
            float wv = expf(wbuf[w][j] - m);
            wbuf[w][j] = wv;
            ss += wv;
        }
        ss = wredsum(ss);
        __syncwarp();
        float inv = 1.f / ss;
        float a0 = 0.f, a1 = 0.f;
        #pragma unroll 8
        for (int j = 0; j < deg; j++) {
            int t = cbuf[w][j];
            float wv = wbuf[w][j];
            float2 v = __half22float2(hb[t * 32]);
            a0 = fmaf(wv, v.x, a0);
            a1 = fmaf(wv, v.y, a1);
        }
        o0 = a0 * inv; o1 = a1 * inv;
    } else if (deg > 128) {   // rare fallback
        float s1i = g_s1[h * Nn + i];
        const float* s2p = g_s2 + h * Nn;
        float m = -1e30f;
        for (int p = p0 + lane; p < p1; p += 32) {
            float e = s1i + s2p[g_col[p]];
            e = e > 0.f ? e : LALPHA * e;
            m = fmaxf(m, e);
        }
        m = wredmax(m);
        float ss = 0.f;
        for (int p = p0 + lane; p < p1; p += 32) {
            float e = s1i + s2p[g_col[p]];
            e = e > 0.f ? e : LALPHA * e;
            ss += expf(e - m);
        }
        ss = wredsum(ss);
        float inv = 1.f / ss;
        float a0 = 0.f, a1 = 0.f;
        for (int p = p0; p < p1; p++) {
            int t = g_col[p];
            float e = s1i + s2p[t];
            e = e > 0.f ? e : LALPHA * e;
            float wv = expf(e - m) * inv;
            float2 v = __half22float2(hb[t * 32]);
            a0 = fmaf(wv, v.x, a0);
            a1 = fmaf(wv, v.y, a1);
        }
        o0 = a0; o1 = a1;
    }
    int c0 = h * HID + 2 * lane;
    o0 += b_heads[c0];
    o1 += b_heads[c0 + 1];
    o0 = o0 > 0.f ? o0 : expm1f(o0);   // elu
    o1 = o1 > 0.f ? o1 : expm1f(o1);
    *(__half2*)(g_xh + i * 512 + c0) = __floats2half2_rn(o0, o1);
}

// ------ GEMM2: smem-staged x (16 rows) + fp16 W, fused layer-2 scores ------
#define LDX 520
__global__ void __launch_bounds__(256) k_gemm2(const float* __restrict__ Wout,
                                               const float* __restrict__ a_out) {
    __shared__ __half WsT[NC][LDX];   // transposed, padded (halves)
    __shared__ __half xs[16][LDX];
    int tid = threadIdx.x;
    for (int j = tid; j < 512 * NC; j += 256)
        WsT[j & 15][j >> 4] = __float2half_rn(Wout[j]);
    int row0 = blockIdx.x * 16;
    const uint4* xsrc = (const uint4*)(g_xh + row0 * 512);
    for (int j = tid; j < 16 * 64; j += 256) {       // 64 uint4 per row
        int r = j >> 6, off = j & 63;
        ((uint4*)&xs[r][0])[off] = xsrc[r * 64 + off];
    }
    __syncthreads();
    int col = tid & 15, rs = tid >> 4;
    int row = row0 + rs;
    const __half2* xp = (const __half2*)&xs[rs][0];
    const __half2* wp = (const __half2*)&WsT[col][0];
    float a0 = 0.f, a1 = 0.f, a2 = 0.f, a3 = 0.f;
    #pragma unroll 8
    for (int k = 0; k < 256; k += 2) {
        float2 x0 = __half22float2(xp[k]);
        float2 w0 = __half22float2(wp[k]);
        float2 x1 = __half22float2(xp[k + 1]);
        float2 w1 = __half22float2(wp[k + 1]);
        a0 = fmaf(x0.x, w0.x, a0);
        a1 = fmaf(x0.y, w0.y, a1);
        a2 = fmaf(x1.x, w1.x, a2);
        a3 = fmaf(x1.y, w1.y, a3);
    }
    float v = (a0 + a1) + (a2 + a3);
    g_h2h[row * NC + col] = __float2half_rn(v);
    // fused scores2
    float q1 = v * a_out[col];
    float q2 = v * a_out[16 + col];
    #pragma unroll
    for (int o = 8; o; o >>= 1) {
        q1 += __shfl_xor_sync(0xffffffffu, q1, o);
        q2 += __shfl_xor_sync(0xffffffffu, q2, o);
    }
    if (col == 0) { g_t1[row] = q1; g_t2[row] = q2; }
}

// ---------------- layer-2 aggregation + log_softmax ----------------
__global__ void __launch_bounds__(256) k_agg2(const float* __restrict__ b_out,
                                              float* __restrict__ out) {
    __shared__ float wbuf[8][132];
    __shared__ int   cbuf[8][132];
    int wid = threadIdx.x >> 5, lane = threadIdx.x & 31;
    int grp = lane >> 4, l16 = lane & 15;
    int i = blockIdx.x * 8 + wid;
    int p0 = g_rowptr[i], p1 = g_rowptr[i + 1];
    int deg = p1 - p0;
    float logit = 0.f;
    if (deg > 0 && deg <= 128) {
        float t1i = g_t1[i];
        float m = -1e30f;
        for (int j = lane; j < deg; j += 32) {
            int t = g_col[p0 + j];
            cbuf[wid][j] = t;
            float e = t1i + g_t2[t];
            e = e > 0.f ? e : LALPHA * e;
            wbuf[wid][j] = e;
            m = fmaxf(m, e);
        }
        m = wredmax(m);
        float ss = 0.f;
        for (int j = lane; j < deg; j += 32) {
            float w = expf(wbuf[wid][j] - m);
            wbuf[wid][j] = w;
            ss += w;
        }
        ss = wredsum(ss);
        __syncwarp();
        float inv = 1.f / ss;
        // split-half apply: group 0 = even edges, group 1 = odd edges
        float acc = 0.f;
        #pragma unroll 4
        for (int j = grp; j < deg; j += 2) {
            int t = cbuf[wid][j];
            float w = wbuf[wid][j];
            acc = fmaf(w, __half2float(g_h2h[t * NC + l16]), acc);
        }
        acc += __shfl_xor_sync(0xffffffffu, acc, 16);
        if (lane < 16) logit = acc * inv + b_out[lane];
    } else if (deg > 128) {
        float t1i = g_t1[i];
        float m = -1e30f;
        for (int p = p0 + lane; p < p1; p += 32) {
            float e = t1i + g_t2[g_col[p]];
            e = e > 0.f ? e : LALPHA * e;
            m = fmaxf(m, e);
        }
        m = wredmax(m);
        float ss = 0.f;
        for (int p = p0 + lane; p < p1; p += 32) {
            float e = t1i + g_t2[g_col[p]];
            e = e > 0.f ? e : LALPHA * e;
            ss += expf(e - m);
        }
        ss = wredsum(ss);
        float inv = 1.f / ss;
        float acc = 0.f;
        for (int p = p0 + grp; p < p1; p += 2) {
            int t = g_col[p];
            float e = t1i + g_t2[t];
            e = e > 0.f ? e : LALPHA * e;
            float w = expf(e - m) * inv;
            acc = fmaf(w, __half2float(g_h2h[t * NC + l16]), acc);
        }
        acc += __shfl_xor_sync(0xffffffffu, acc, 16);
        if (lane < 16) logit = acc + b_out[lane];
    } else {
        if (lane < 16) logit = b_out[lane];   // deg==0: unreachable on this dataset
    }
    // log_softmax over 16 classes
    float lm = (lane < 16) ? logit : -1e30f;
    #pragma unroll
    for (int o = 8; o; o >>= 1) lm = fmaxf(lm, __shfl_xor_sync(0xffffffffu, lm, o));
    float es = (lane < 16) ? expf(logit - lm) : 0.f;
    #pragma unroll
    for (int o = 8; o; o >>= 1) es += __shfl_xor_sync(0xffffffffu, es, o);
    if (lane < 16) out[i * NC + lane] = logit - lm - logf(es);
}

// ---------------- side stream (created once, host resources only) ----------
struct SideStream {
    cudaStream_t s2;
    cudaEvent_t eFork, eJoin;
    SideStream() {
        cudaStreamCreateWithFlags(&s2, cudaStreamNonBlocking);
        cudaEventCreateWithFlags(&eFork, cudaEventDisableTiming);
        cudaEventCreateWithFlags(&eJoin, cudaEventDisableTiming);
    }
};
static SideStream g_ss;

// ---------------- launch ----------------
extern "C" void kernel_launch(void* const* d_in, const int* in_sizes, int n_in,
                              void* d_out, int out_size) {
    const float* features    = (const float*)d_in[0];
    const int* el            = (const int*)d_in[1];
    const float* W_heads     = (const float*)d_in[2];
    const float* a_heads     = (const float*)d_in[3];
    const float* b_heads     = (const float*)d_in[4];
    const float* W_out       = (const float*)d_in[5];
    const float* a_out       = (const float*)d_in[6];
    const float* b_out       = (const float*)d_in[7];
    float* out = (float*)d_out;

    // fork: graph-build chain on side stream
    cudaEventRecord(g_ss.eFork, 0);
    cudaStreamWaitEvent(g_ss.s2, g_ss.eFork, 0);
    k_clear_graph<<<(Nn * Nn / 128 + 255) / 256, 256, 0, g_ss.s2>>>();
    k_dedup<<<Ee / 1024, 256, 0, g_ss.s2>>>(el);
    k_scan<<<1, 1024, 0, g_ss.s2>>>();
    k_scatter<<<Ee / 1024, 256, 0, g_ss.s2>>>(el);
    cudaEventRecord(g_ss.eJoin, g_ss.s2);

    // main chain: compute
    k_tohalf<<<(Nn * FIN / 4 + FIN * 512 / 4 + 255) / 256, 256>>>(features, W_heads);
    k_gemm1_mma<<<dim3(4, 32), 256>>>(a_heads);

    // join, then the dependent tail
    cudaStreamWaitEvent(0, g_ss.eJoin, 0);
    k_agg1<<<dim3(Nn / 8, NH), 256>>>(b_heads);
    k_gemm2<<<Nn / 16, 256>>>(W_out, a_out);
    k_agg2<<<Nn / 8, 256>>>(b_out, out);
}

// round 13
// speedup vs baseline: 1.1048x; 1.0269x over previous
#include <cuda_runtime.h>
#include <cuda_fp16.h>

#define Nn 4096
#define Ee 262144
#define FIN 512
#define HID 64
#define NH 8
#define NC 16
#define LALPHA 0.2f

// ---------------- scratch (static __device__, no allocations) ----------------
__device__ unsigned g_bitmap[Nn * Nn / 32];   // 2MB dedup bitmap
__device__ int g_deg[Nn];
__device__ int g_rowptr[Nn + 1];
__device__ int g_rnk[Ee];                     // rank+1 within row, 0 = duplicate
__device__ int g_col[Ee];
__device__ __half g_Ahi[Nn * FIN];                      // fp16 features
__device__ __half g_Whi[FIN * 512], g_Wlo[FIN * 512];   // exact-split Wcat
__device__ __half g_h1h[NH * Nn * HID];       // layer1 h fp16, HEAD-MAJOR [h][n][64]
__device__ __half g_xh[Nn * 512];             // elu(att@h + b) fp16 (4MB), node-major
__device__ float g_s1[NH * Nn];
__device__ float g_s2[NH * Nn];
__device__ __half g_h2h[Nn * NC];             // layer2 h fp16 (128KB)
__device__ float g_t1[Nn];
__device__ float g_t2[Nn];

// ---------------- helpers ----------------
__device__ __forceinline__ float wredsum(float v) {
    #pragma unroll
    for (int o = 16; o; o >>= 1) v += __shfl_xor_sync(0xffffffffu, v, o);
    return v;
}
__device__ __forceinline__ float wredmax(float v) {
    #pragma unroll
    for (int o = 16; o; o >>= 1) v = fmaxf(v, __shfl_xor_sync(0xffffffffu, v, o));
    return v;
}

__device__ __forceinline__ void ldm_x4(unsigned* r, const void* p) {
    unsigned a = (unsigned)__cvta_generic_to_shared(p);
    asm volatile("ldmatrix.sync.aligned.m8n8.x4.shared.b16 {%0,%1,%2,%3}, [%4];"
        : "=r"(r[0]), "=r"(r[1]), "=r"(r[2]), "=r"(r[3]) : "r"(a));
}
__device__ __forceinline__ void ldm_x2t(unsigned* r, const void* p) {
    unsigned a = (unsigned)__cvta_generic_to_shared(p);
    asm volatile("ldmatrix.sync.aligned.m8n8.x2.trans.shared.b16 {%0,%1}, [%2];"
        : "=r"(r[0]), "=r"(r[1]) : "r"(a));
}
__device__ __forceinline__ void mma16816(float* c, const unsigned* a, const unsigned* b) {
    asm volatile("mma.sync.aligned.m16n8k16.row.col.f32.f16.f16.f32 "
        "{%0,%1,%2,%3}, {%4,%5,%6,%7}, {%8,%9}, {%0,%1,%2,%3};"
        : "+f"(c[0]), "+f"(c[1]), "+f"(c[2]), "+f"(c[3])
        : "r"(a[0]), "r"(a[1]), "r"(a[2]), "r"(a[3]), "r"(b[0]), "r"(b[1]));
}

// ---------------- graph build (stream 2) ----------------
__global__ void k_clear_graph() {
    int i = blockIdx.x * blockDim.x + threadIdx.x;
    if (i < Nn * Nn / 128) ((uint4*)g_bitmap)[i] = make_uint4(0, 0, 0, 0);
    if (i < Nn) g_deg[i] = 0;
}

__global__ void k_dedup(const int* __restrict__ el) {   // 2 edges/thread
    int b = 2 * (blockIdx.x * blockDim.x + threadIdx.x);
    if (b >= Ee) return;
    int2 sv = *(const int2*)(el + b);
    int2 tv = *(const int2*)(el + Ee + b);
    int ss[2] = {sv.x, sv.y};
    int tt[2] = {tv.x, tv.y};
    unsigned old[2];
    #pragma unroll
    for (int q = 0; q < 2; q++) {
        unsigned idx = ((unsigned)ss[q] << 12) | (unsigned)tt[q];
        old[q] = atomicOr(&g_bitmap[idx >> 5], 1u << (idx & 31));
    }
    int2 rk;
    int* rkp = (int*)&rk;
    #pragma unroll
    for (int q = 0; q < 2; q++) {
        unsigned idx = ((unsigned)ss[q] << 12) | (unsigned)tt[q];
        bool isnew = !(old[q] & (1u << (idx & 31)));
        rkp[q] = isnew ? (atomicAdd(&g_deg[ss[q]], 1) + 1) : 0;
    }
    *(int2*)(g_rnk + b) = rk;
}

__global__ void k_scan() {   // 1 block, 1024 threads, warp-shuffle scan
    __shared__ int warpsum[32];
    int tid = threadIdx.x;
    int lane = tid & 31, wid = tid >> 5;
    int v0 = g_deg[4 * tid + 0];
    int v1 = g_deg[4 * tid + 1];
    int v2 = g_deg[4 * tid + 2];
    int v3 = g_deg[4 * tid + 3];
    int tot = v0 + v1 + v2 + v3;
    int s = tot;
    #pragma unroll
    for (int o = 1; o < 32; o <<= 1) {
        int t = __shfl_up_sync(0xffffffffu, s, o);
        if (lane >= o) s += t;
    }
    if (lane == 31) warpsum[wid] = s;
    __syncthreads();
    if (wid == 0) {
        int ws = warpsum[lane];
        #pragma unroll
        for (int o = 1; o < 32; o <<= 1) {
            int t = __shfl_up_sync(0xffffffffu, ws, o);
            if (lane >= o) ws += t;
        }
        warpsum[lane] = ws;
    }
    __syncthreads();
    int p = (wid ? warpsum[wid - 1] : 0) + s - tot;   // exclusive prefix
    g_rowptr[4 * tid + 0] = p; p += v0;
    g_rowptr[4 * tid + 1] = p; p += v1;
    g_rowptr[4 * tid + 2] = p; p += v2;
    g_rowptr[4 * tid + 3] = p; p += v3;
    if (tid == 1023) g_rowptr[Nn] = warpsum[31];
}

__global__ void k_scatter(const int* __restrict__ el) {  // atomic-free, 2/thread
    int b = 2 * (blockIdx.x * blockDim.x + threadIdx.x);
    if (b >= Ee) return;
    int2 sv = *(const int2*)(el + b);
    int2 tv = *(const int2*)(el + Ee + b);
    int2 rv = *(const int2*)(g_rnk + b);
    if (rv.x) g_col[g_rowptr[sv.x] + rv.x - 1] = tv.x;
    if (rv.y) g_col[g_rowptr[sv.y] + rv.y - 1] = tv.y;
}

// ---------------- fp32 -> fp16 A, exact (hi,lo) split of Wcat ----------------
__global__ void k_tohalf(const float* __restrict__ A, const float* __restrict__ Wh) {
    int i = blockIdx.x * blockDim.x + threadIdx.x;   // float4 group
    const int NA4 = Nn * FIN / 4;
    if (i < NA4) {
        float4 v = ((const float4*)A)[i];
        ((__half2*)g_Ahi)[2 * i] = __floats2half2_rn(v.x, v.y);
        ((__half2*)g_Ahi)[2 * i + 1] = __floats2half2_rn(v.z, v.w);
    } else if (i < NA4 + FIN * 512 / 4) {
        int j = (i - NA4) * 4;           // element index in Wcat [FIN][512]
        int k = j >> 9, c = j & 511;
        int hh = c >> 6, jj = c & 63;
        float4 v = *(const float4*)(Wh + hh * (FIN * HID) + k * HID + jj);
        __half h0 = __float2half_rn(v.x), h1 = __float2half_rn(v.y);
        __half h2 = __float2half_rn(v.z), h3 = __float2half_rn(v.w);
        __half2* dst_hi = (__half2*)(g_Whi + k * 512 + c);
        __half2* dst_lo = (__half2*)(g_Wlo + k * 512 + c);
        dst_hi[0] = __halves2half2(h0, h1);
        dst_hi[1] = __halves2half2(h2, h3);
        dst_lo[0] = __halves2half2(
            __float2half_rn(v.x - __half2float(h0)), __float2half_rn(v.y - __half2float(h1)));
        dst_lo[1] = __halves2half2(
            __float2half_rn(v.z - __half2float(h2)), __float2half_rn(v.w - __half2float(h3)));
    }
}

// ---- GEMM1 (128x128, 2-term split) with FUSED per-node score epilogue ------
#define BM 128
#define BN 128
#define BK 32
#define LDA 40
#define LDB 136

__global__ void __launch_bounds__(256) k_gemm1_mma(const float* __restrict__ a_heads) {
    __shared__ __half As[BM][LDA];
    __shared__ __half Bs_hi[BK][LDB], Bs_lo[BK][LDB];
    __shared__ float sred[128][2][2][2];   // [row][head-local][p1/p2][wn parity]
    int tid = threadIdx.x;
    int wid = tid >> 5, lane = tid & 31;
    int wm = wid & 1, wn = wid >> 1;          // warp tile: 64x32
    int row0 = blockIdx.y * BM, col0 = blockIdx.x * BN;

    int arow = tid >> 1, acol = (tid & 1) * 16;   // 16 halves of A per thread
    int bkrow = tid >> 3, bn = (tid & 7) * 16;    // 16 halves of B per thread
    const __half* aph = g_Ahi + (row0 + arow) * FIN + acol;
    const __half* bph = g_Whi + bkrow * 512 + col0 + bn;
    const __half* bpl = g_Wlo + bkrow * 512 + col0 + bn;

    uint4 rah[2], rbh[2], rbl[2];
    rah[0] = *(const uint4*)(aph);     rah[1] = *(const uint4*)(aph + 8);
    rbh[0] = *(const uint4*)(bph);     rbh[1] = *(const uint4*)(bph + 8);
    rbl[0] = *(const uint4*)(bpl);     rbl[1] = *(const uint4*)(bpl + 8);

    float acc[4][4][4];
    #pragma unroll
    for (int mi = 0; mi < 4; mi++)
        #pragma unroll
        for (int ni = 0; ni < 4; ni++)
            #pragma unroll
            for (int q = 0; q < 4; q++) acc[mi][ni][q] = 0.f;

    for (int k0 = 0; k0 < FIN; k0 += BK) {
        *(uint4*)&As[arow][acol] = rah[0];
        *(uint4*)&As[arow][acol + 8] = rah[1];
        *(uint4*)&Bs_hi[bkrow][bn] = rbh[0];
        *(uint4*)&Bs_hi[bkrow][bn + 8] = rbh[1];
        *(uint4*)&Bs_lo[bkrow][bn] = rbl[0];
        *(uint4*)&Bs_lo[bkrow][bn + 8] = rbl[1];
        __syncthreads();
        if (k0 + BK < FIN) {
            rah[0] = *(const uint4*)(aph + k0 + BK);
            rah[1] = *(const uint4*)(aph + k0 + BK + 8);
            rbh[0] = *(const uint4*)(bph + (k0 + BK) * 512);
            rbh[1] = *(const uint4*)(bph + (k0 + BK) * 512 + 8);
            rbl[0] = *(const uint4*)(bpl + (k0 + BK) * 512);
            rbl[1] = *(const uint4*)(bpl + (k0 + BK) * 512 + 8);
        }
        #pragma unroll
        for (int ks = 0; ks < BK; ks += 16) {
            unsigned af[4][4], bfh[4][2], bfl[4][2];
            #pragma unroll
            for (int mi = 0; mi < 4; mi++) {
                int r = wm * 64 + mi * 16 + (lane & 15);
                int c = ks + (lane >> 4) * 8;
                ldm_x4(af[mi], &As[r][c]);
            }
            #pragma unroll
            for (int ni = 0; ni < 4; ni++) {
                int kr = ks + (lane & 15);
                int nc = wn * 32 + ni * 8;
                ldm_x2t(bfh[ni], &Bs_hi[kr][nc]);
                ldm_x2t(bfl[ni], &Bs_lo[kr][nc]);
            }
            #pragma unroll
            for (int mi = 0; mi < 4; mi++)
                #pragma unroll
                for (int ni = 0; ni < 4; ni++) {
                    mma16816(acc[mi][ni], af[mi], bfh[ni]);
                    mma16816(acc[mi][ni], af[mi], bfl[ni]);
                }
        }
        __syncthreads();
    }
    // h1h stores — HEAD-MAJOR: g_h1h[head][node][64]
    #pragma unroll
    for (int mi = 0; mi < 4; mi++)
        #pragma unroll
        for (int ni = 0; ni < 4; ni++) {
            int r = row0 + wm * 64 + mi * 16 + (lane >> 2);
            int c = col0 + wn * 32 + ni * 8 + (lane & 3) * 2;
            int head = c >> 6, cl = c & 63;
            __half* base = g_h1h + ((size_t)head * Nn) * HID + cl;
            *(__half2*)(base + r * HID) =
                __floats2half2_rn(acc[mi][ni][0], acc[mi][ni][1]);
            *(__half2*)(base + (r + 8) * HID) =
                __floats2half2_rn(acc[mi][ni][2], acc[mi][ni][3]);
        }
    // fused per-node score epilogue
    {
        int hl = wn >> 1;
        int par = wn & 1;
        const float* av = a_heads + (2 * blockIdx.x + hl) * 128;
        float a1v[8], a2v[8];
        #pragma unroll
        for (int ni = 0; ni < 4; ni++) {
            int cl = par * 32 + ni * 8 + (lane & 3) * 2;  // head-local col (0..63)
            a1v[2 * ni] = av[cl];       a1v[2 * ni + 1] = av[cl + 1];
            a2v[2 * ni] = av[64 + cl];  a2v[2 * ni + 1] = av[65 + cl];
        }
        #pragma unroll
        for (int mi = 0; mi < 4; mi++) {
            float p1a = 0.f, p2a = 0.f, p1b = 0.f, p2b = 0.f;
            #pragma unroll
            for (int ni = 0; ni < 4; ni++) {
                p1a += acc[mi][ni][0] * a1v[2 * ni] + acc[mi][ni][1] * a1v[2 * ni + 1];
                p2a += acc[mi][ni][0] * a2v[2 * ni] + acc[mi][ni][1] * a2v[2 * ni + 1];
                p1b += acc[mi][ni][2] * a1v[2 * ni] + acc[mi][ni][3] * a1v[2 * ni + 1];
                p2b += acc[mi][ni][2] * a2v[2 * ni] + acc[mi][ni][3] * a2v[2 * ni + 1];
            }
            #pragma unroll
            for (int o = 1; o <= 2; o <<= 1) {
                p1a += __shfl_xor_sync(0xffffffffu, p1a, o);
                p2a += __shfl_xor_sync(0xffffffffu, p2a, o);
                p1b += __shfl_xor_sync(0xffffffffu, p1b, o);
                p2b += __shfl_xor_sync(0xffffffffu, p2b, o);
            }
            if ((lane & 3) == 0) {
                int r = wm * 64 + mi * 16 + (lane >> 2);
                sred[r][hl][0][par] = p1a;
                sred[r][hl][1][par] = p2a;
                sred[r + 8][hl][0][par] = p1b;
                sred[r + 8][hl][1][par] = p2b;
            }
        }
        __syncthreads();
        for (int o = tid; o < 512; o += 256) {
            int r = o & 127, hh = (o >> 7) & 1, p = (o >> 8) & 1;
            float val = sred[r][hh][p][0] + sred[r][hh][p][1];
            float* dst = p ? g_s2 : g_s1;
            dst[(2 * blockIdx.x + hh) * Nn + row0 + r] = val;
        }
    }
}

// ------- layer-1 aggregation: 2 warps per (node, head), edge-parity split ---
// grid (Nn/4, NH), block 256 = 4 pairs. Pair p handles node blockIdx.x*4+p.
__global__ void __launch_bounds__(256) k_agg1(const float* __restrict__ b_heads) {
    __shared__ float wbuf[4][136];
    __shared__ int   cbuf[4][136];
    __shared__ float redm[4][2];
    __shared__ float reds[4][2];
    __shared__ float acc2[4][32][2];   // sub==1 partials
    int w = threadIdx.x >> 5, lane = threadIdx.x & 31;
    int pair = w >> 1, sub = w & 1;
    int i = blockIdx.x * 4 + pair;
    int h = blockIdx.y;
    int p0 = g_rowptr[i], p1 = g_rowptr[i + 1];
    int deg = p1 - p0;
    bool small = (deg <= 128);
    const __half2* hb = ((const __half2*)g_h1h) + (size_t)h * Nn * 32 + lane;
    float s1i = g_s1[h * Nn + i];
    const float* s2p = g_s2 + h * Nn;

    // pass 1: scores + max (this warp: edges j ≡ sub mod 2, lane-strided)
    float m = -1e30f;
    for (int j = 2 * lane + sub; j < deg; j += 64) {
        int t = g_col[p0 + j];
        float e = s1i + s2p[t];
        e = e > 0.f ? e : LALPHA * e;
        if (small) { cbuf[pair][j] = t; wbuf[pair][j] = e; }
        m = fmaxf(m, e);
    }
    m = wredmax(m);
    if (lane == 0) redm[pair][sub] = m;
    __syncthreads();
    m = fmaxf(redm[pair][0], redm[pair][1]);

    // pass 2: exp + sum
    float ss = 0.f;
    if (small) {
        for (int j = 2 * lane + sub; j < deg; j += 64) {
            float wv = expf(wbuf[pair][j] - m);
            wbuf[pair][j] = wv;
            ss += wv;
        }
    } else {
        for (int j = 2 * lane + sub; j < deg; j += 64) {
            int t = g_col[p0 + j];
            float e = s1i + s2p[t];
            e = e > 0.f ? e : LALPHA * e;
            ss += expf(e - m);
        }
    }
    ss = wredsum(ss);
    if (lane == 0) reds[pair][sub] = ss;
    __syncthreads();
    float sums = reds[pair][0] + reds[pair][1];
    float inv = (sums > 0.f) ? 1.f / sums : 0.f;

    // apply: warp sub handles edges j ≡ sub (mod 2), serial; lanes over dims
    float a0 = 0.f, a1 = 0.f;
    if (small) {
        #pragma unroll 4
        for (int j = sub; j < deg; j += 2) {
            int t = cbuf[pair][j];
            float wv = wbuf[pair][j];
            float2 v = __half22float2(hb[t * 32]);
            a0 = fmaf(wv, v.x, a0);
            a1 = fmaf(wv, v.y, a1);
        }
    } else {
        for (int j = sub; j < deg; j += 2) {
            int t = g_col[p0 + j];
            float e = s1i + s2p[t];
            e = e > 0.f ? e : LALPHA * e;
            float wv = expf(e - m);
            float2 v = __half22float2(hb[t * 32]);
            a0 = fmaf(wv, v.x, a0);
            a1 = fmaf(wv, v.y, a1);
        }
    }
    if (sub == 1) { acc2[pair][lane][0] = a0; acc2[pair][lane][1] = a1; }
    __syncthreads();
    if (sub == 0) {
        float o0 = (a0 + acc2[pair][lane][0]) * inv;
        float o1 = (a1 + acc2[pair][lane][1]) * inv;
        int c0 = h * HID + 2 * lane;
        o0 += b_heads[c0];
        o1 += b_heads[c0 + 1];
        o0 = o0 > 0.f ? o0 : expm1f(o0);   // elu
        o1 = o1 > 0.f ? o1 : expm1f(o1);
        *(__half2*)(g_xh + i * 512 + c0) = __floats2half2_rn(o0, o1);
    }
}

// ------ GEMM2: smem-staged x (16 rows) + fp16 W, fused layer-2 scores ------
#define LDX 520
__global__ void __launch_bounds__(256) k_gemm2(const float* __restrict__ Wout,
                                               const float* __restrict__ a_out) {
    __shared__ __half WsT[NC][LDX];   // transposed, padded (halves)
    __shared__ __half xs[16][LDX];
    int tid = threadIdx.x;
    for (int j = tid; j < 512 * NC; j += 256)
        WsT[j & 15][j >> 4] = __float2half_rn(Wout[j]);
    int row0 = blockIdx.x * 16;
    const uint4* xsrc = (const uint4*)(g_xh + row0 * 512);
    for (int j = tid; j < 16 * 64; j += 256) {       // 64 uint4 per row
        int r = j >> 6, off = j & 63;
        ((uint4*)&xs[r][0])[off] = xsrc[r * 64 + off];
    }
    __syncthreads();
    int col = tid & 15, rs = tid >> 4;
    int row = row0 + rs;
    const __half2* xp = (const __half2*)&xs[rs][0];
    const __half2* wp = (const __half2*)&WsT[col][0];
    float a0 = 0.f, a1 = 0.f, a2 = 0.f, a3 = 0.f;
    #pragma unroll 8
    for (int k = 0; k < 256; k += 2) {
        float2 x0 = __half22float2(xp[k]);
        float2 w0 = __half22float2(wp[k]);
        float2 x1 = __half22float2(xp[k + 1]);
        float2 w1 = __half22float2(wp[k + 1]);
        a0 = fmaf(x0.x, w0.x, a0);
        a1 = fmaf(x0.y, w0.y, a1);
        a2 = fmaf(x1.x, w1.x, a2);
        a3 = fmaf(x1.y, w1.y, a3);
    }
    float v = (a0 + a1) + (a2 + a3);
    g_h2h[row * NC + col] = __float2half_rn(v);
    // fused scores2
    float q1 = v * a_out[col];
    float q2 = v * a_out[16 + col];
    #pragma unroll
    for (int o = 8; o; o >>= 1) {
        q1 += __shfl_xor_sync(0xffffffffu, q1, o);
        q2 += __shfl_xor_sync(0xffffffffu, q2, o);
    }
    if (col == 0) { g_t1[row] = q1; g_t2[row] = q2; }
}

// ---------------- layer-2 aggregation + log_softmax ----------------
__global__ void __launch_bounds__(256) k_agg2(const float* __restrict__ b_out,
                                              float* __restrict__ out) {
    __shared__ float wbuf[8][132];
    __shared__ int   cbuf[8][132];
    int wid = threadIdx.x >> 5, lane = threadIdx.x & 31;
    int grp = lane >> 4, l16 = lane & 15;
    int i = blockIdx.x * 8 + wid;
    int p0 = g_rowptr[i], p1 = g_rowptr[i + 1];
    int deg = p1 - p0;
    float logit = 0.f;
    if (deg > 0 && deg <= 128) {
        float t1i = g_t1[i];
        float m = -1e30f;
        for (int j = lane; j < deg; j += 32) {
            int t = g_col[p0 + j];
            cbuf[wid][j] = t;
            float e = t1i + g_t2[t];
            e = e > 0.f ? e : LALPHA * e;
            wbuf[wid][j] = e;
            m = fmaxf(m, e);
        }
        m = wredmax(m);
        float ss = 0.f;
        for (int j = lane; j < deg; j += 32) {
            float w = expf(wbuf[wid][j] - m);
            wbuf[wid][j] = w;
            ss += w;
        }
        ss = wredsum(ss);
        __syncwarp();
        float inv = 1.f / ss;
        float acc = 0.f;
        #pragma unroll 4
        for (int j = grp; j < deg; j += 2) {
            int t = cbuf[wid][j];
            float w = wbuf[wid][j];
            acc = fmaf(w, __half2float(g_h2h[t * NC + l16]), acc);
        }
        acc += __shfl_xor_sync(0xffffffffu, acc, 16);
        if (lane < 16) logit = acc * inv + b_out[lane];
    } else if (deg > 128) {
        float t1i = g_t1[i];
        float m = -1e30f;
        for (int p = p0 + lane; p < p1; p += 32) {
            float e = t1i + g_t2[g_col[p]];
            e = e > 0.f ? e : LALPHA * e;
            m = fmaxf(m, e);
        }
        m = wredmax(m);
        float ss = 0.f;
        for (int p = p0 + lane; p < p1; p += 32) {
            float e = t1i + g_t2[g_col[p]];
            e = e > 0.f ? e : LALPHA * e;
            ss += expf(e - m);
        }
        ss = wredsum(ss);
        float inv = 1.f / ss;
        float acc = 0.f;
        for (int p = p0 + grp; p < p1; p += 2) {
            int t = g_col[p];
            float e = t1i + g_t2[t];
            e = e > 0.f ? e : LALPHA * e;
            float w = expf(e - m) * inv;
            acc = fmaf(w, __half2float(g_h2h[t * NC + l16]), acc);
        }
        acc += __shfl_xor_sync(0xffffffffu, acc, 16);
        if (lane < 16) logit = acc + b_out[lane];
    } else {
        if (lane < 16) logit = b_out[lane];   // deg==0: unreachable on this dataset
    }
    // log_softmax over 16 classes
    float lm = (lane < 16) ? logit : -1e30f;
    #pragma unroll
    for (int o = 8; o; o >>= 1) lm = fmaxf(lm, __shfl_xor_sync(0xffffffffu, lm, o));
    float es = (lane < 16) ? expf(logit - lm) : 0.f;
    #pragma unroll
    for (int o = 8; o; o >>= 1) es += __shfl_xor_sync(0xffffffffu, es, o);
    if (lane < 16) out[i * NC + lane] = logit - lm - logf(es);
}

// ---------------- side stream (created once, host resources only) ----------
struct SideStream {
    cudaStream_t s2;
    cudaEvent_t eFork, eJoin;
    SideStream() {
        cudaStreamCreateWithFlags(&s2, cudaStreamNonBlocking);
        cudaEventCreateWithFlags(&eFork, cudaEventDisableTiming);
        cudaEventCreateWithFlags(&eJoin, cudaEventDisableTiming);
    }
};
static SideStream g_ss;

// ---------------- launch ----------------
extern "C" void kernel_launch(void* const* d_in, const int* in_sizes, int n_in,
                              void* d_out, int out_size) {
    const float* features    = (const float*)d_in[0];
    const int* el            = (const int*)d_in[1];
    const float* W_heads     = (const float*)d_in[2];
    const float* a_heads     = (const float*)d_in[3];
    const float* b_heads     = (const float*)d_in[4];
    const float* W_out       = (const float*)d_in[5];
    const float* a_out       = (const float*)d_in[6];
    const float* b_out       = (const float*)d_in[7];
    float* out = (float*)d_out;

    // fork: graph-build chain on side stream
    cudaEventRecord(g_ss.eFork, 0);
    cudaStreamWaitEvent(g_ss.s2, g_ss.eFork, 0);
    k_clear_graph<<<(Nn * Nn / 128 + 255) / 256, 256, 0, g_ss.s2>>>();
    k_dedup<<<Ee / 512, 256, 0, g_ss.s2>>>(el);
    k_scan<<<1, 1024, 0, g_ss.s2>>>();
    k_scatter<<<Ee / 512, 256, 0, g_ss.s2>>>(el);
    cudaEventRecord(g_ss.eJoin, g_ss.s2);

    // main chain: compute
    k_tohalf<<<(Nn * FIN / 4 + FIN * 512 / 4 + 255) / 256, 256>>>(features, W_heads);
    k_gemm1_mma<<<dim3(4, 32), 256>>>(a_heads);

    // join, then the dependent tail
    cudaStreamWaitEvent(0, g_ss.eJoin, 0);
    k_agg1<<<dim3(Nn / 4, NH), 256>>>(b_heads);
    k_gemm2<<<Nn / 16, 256>>>(W_out, a_out);
    k_agg2<<<Nn / 8, 256>>>(b_out, out);
}

// round 14
// speedup vs baseline: 1.1170x; 1.0111x over previous
#include <cuda_runtime.h>
#include <cuda_fp16.h>

#define Nn 4096
#define Ee 262144
#define FIN 512
#define HID 64
#define NH 8
#define NC 16
#define LALPHA 0.2f

// ---------------- scratch (static __device__, no allocations) ----------------
__device__ unsigned g_bitmap[Nn * Nn / 32];   // 2MB dedup bitmap
__device__ int g_deg[Nn];
__device__ int g_rowptr[Nn + 1];
__device__ int g_rnk[Ee];                     // rank+1 within row, 0 = duplicate
__device__ int g_col[Ee];
__device__ __half g_Ahi[Nn * FIN];                      // fp16 features
__device__ __half g_Whi[FIN * 512], g_Wlo[FIN * 512];   // exact-split Wcat
__device__ __half g_h1h[NH * Nn * HID];       // layer1 h fp16, HEAD-MAJOR [h][n][64]
__device__ __half g_xh[Nn * 512];             // elu(att@h + b) fp16 (4MB), node-major
__device__ float g_s1[NH * Nn];
__device__ float g_s2[NH * Nn];
__device__ __half g_h2h[Nn * NC];             // layer2 h fp16 (128KB)
__device__ float g_t1[Nn];
__device__ float g_t2[Nn];

// ---------------- helpers ----------------
__device__ __forceinline__ float wredsum(float v) {
    #pragma unroll
    for (int o = 16; o; o >>= 1) v += __shfl_xor_sync(0xffffffffu, v, o);
    return v;
}
__device__ __forceinline__ float wredmax(float v) {
    #pragma unroll
    for (int o = 16; o; o >>= 1) v = fmaxf(v, __shfl_xor_sync(0xffffffffu, v, o));
    return v;
}

__device__ __forceinline__ void ldm_x4(unsigned* r, const void* p) {
    unsigned a = (unsigned)__cvta_generic_to_shared(p);
    asm volatile("ldmatrix.sync.aligned.m8n8.x4.shared.b16 {%0,%1,%2,%3}, [%4];"
        : "=r"(r[0]), "=r"(r[1]), "=r"(r[2]), "=r"(r[3]) : "r"(a));
}
__device__ __forceinline__ void ldm_x2t(unsigned* r, const void* p) {
    unsigned a = (unsigned)__cvta_generic_to_shared(p);
    asm volatile("ldmatrix.sync.aligned.m8n8.x2.trans.shared.b16 {%0,%1}, [%2];"
        : "=r"(r[0]), "=r"(r[1]) : "r"(a));
}
__device__ __forceinline__ void mma16816(float* c, const unsigned* a, const unsigned* b) {
    asm volatile("mma.sync.aligned.m16n8k16.row.col.f32.f16.f16.f32 "
        "{%0,%1,%2,%3}, {%4,%5,%6,%7}, {%8,%9}, {%0,%1,%2,%3};"
        : "+f"(c[0]), "+f"(c[1]), "+f"(c[2]), "+f"(c[3])
        : "r"(a[0]), "r"(a[1]), "r"(a[2]), "r"(a[3]), "r"(b[0]), "r"(b[1]));
}

// ---------------- graph build (stream 2) ----------------
__global__ void k_clear_graph() {
    int i = blockIdx.x * blockDim.x + threadIdx.x;
    if (i < Nn * Nn / 128) ((uint4*)g_bitmap)[i] = make_uint4(0, 0, 0, 0);
    if (i < Nn) g_deg[i] = 0;
}

__global__ void k_dedup(const int* __restrict__ el) {   // 2 edges/thread
    int b = 2 * (blockIdx.x * blockDim.x + threadIdx.x);
    if (b >= Ee) return;
    int2 sv = *(const int2*)(el + b);
    int2 tv = *(const int2*)(el + Ee + b);
    int ss[2] = {sv.x, sv.y};
    int tt[2] = {tv.x, tv.y};
    unsigned old[2];
    #pragma unroll
    for (int q = 0; q < 2; q++) {
        unsigned idx = ((unsigned)ss[q] << 12) | (unsigned)tt[q];
        old[q] = atomicOr(&g_bitmap[idx >> 5], 1u << (idx & 31));
    }
    int2 rk;
    int* rkp = (int*)&rk;
    #pragma unroll
    for (int q = 0; q < 2; q++) {
        unsigned idx = ((unsigned)ss[q] << 12) | (unsigned)tt[q];
        bool isnew = !(old[q] & (1u << (idx & 31)));
        rkp[q] = isnew ? (atomicAdd(&g_deg[ss[q]], 1) + 1) : 0;
    }
    *(int2*)(g_rnk + b) = rk;
}

__global__ void k_scan() {   // 1 block, 1024 threads, warp-shuffle scan
    __shared__ int warpsum[32];
    int tid = threadIdx.x;
    int lane = tid & 31, wid = tid >> 5;
    int v0 = g_deg[4 * tid + 0];
    int v1 = g_deg[4 * tid + 1];
    int v2 = g_deg[4 * tid + 2];
    int v3 = g_deg[4 * tid + 3];
    int tot = v0 + v1 + v2 + v3;
    int s = tot;
    #pragma unroll
    for (int o = 1; o < 32; o <<= 1) {
        int t = __shfl_up_sync(0xffffffffu, s, o);
        if (lane >= o) s += t;
    }
    if (lane == 31) warpsum[wid] = s;
    __syncthreads();
    if (wid == 0) {
        int ws = warpsum[lane];
        #pragma unroll
        for (int o = 1; o < 32; o <<= 1) {
            int t = __shfl_up_sync(0xffffffffu, ws, o);
            if (lane >= o) ws += t;
        }
        warpsum[lane] = ws;
    }
    __syncthreads();
    int p = (wid ? warpsum[wid - 1] : 0) + s - tot;   // exclusive prefix
    g_rowptr[4 * tid + 0] = p; p += v0;
    g_rowptr[4 * tid + 1] = p; p += v1;
    g_rowptr[4 * tid + 2] = p; p += v2;
    g_rowptr[4 * tid + 3] = p; p += v3;
    if (tid == 1023) g_rowptr[Nn] = warpsum[31];
}

__global__ void k_scatter(const int* __restrict__ el) {  // atomic-free, 2/thread
    int b = 2 * (blockIdx.x * blockDim.x + threadIdx.x);
    if (b >= Ee) return;
    int2 sv = *(const int2*)(el + b);
    int2 tv = *(const int2*)(el + Ee + b);
    int2 rv = *(const int2*)(g_rnk + b);
    if (rv.x) g_col[g_rowptr[sv.x] + rv.x - 1] = tv.x;
    if (rv.y) g_col[g_rowptr[sv.y] + rv.y - 1] = tv.y;
}

// ---------------- fp32 -> fp16 A, exact (hi,lo) split of Wcat ----------------
__global__ void k_tohalf(const float* __restrict__ A, const float* __restrict__ Wh) {
    int i = blockIdx.x * blockDim.x + threadIdx.x;   // float4 group
    const int NA4 = Nn * FIN / 4;
    if (i < NA4) {
        float4 v = ((const float4*)A)[i];
        ((__half2*)g_Ahi)[2 * i] = __floats2half2_rn(v.x, v.y);
        ((__half2*)g_Ahi)[2 * i + 1] = __floats2half2_rn(v.z, v.w);
    } else if (i < NA4 + FIN * 512 / 4) {
        int j = (i - NA4) * 4;           // element index in Wcat [FIN][512]
        int k = j >> 9, c = j & 511;
        int hh = c >> 6, jj = c & 63;
        float4 v = *(const float4*)(Wh + hh * (FIN * HID) + k * HID + jj);
        __half h0 = __float2half_rn(v.x), h1 = __float2half_rn(v.y);
        __half h2 = __float2half_rn(v.z), h3 = __float2half_rn(v.w);
        __half2* dst_hi = (__half2*)(g_Whi + k * 512 + c);
        __half2* dst_lo = (__half2*)(g_Wlo + k * 512 + c);
        dst_hi[0] = __halves2half2(h0, h1);
        dst_hi[1] = __halves2half2(h2, h3);
        dst_lo[0] = __halves2half2(
            __float2half_rn(v.x - __half2float(h0)), __float2half_rn(v.y - __half2float(h1)));
        dst_lo[1] = __halves2half2(
            __float2half_rn(v.z - __half2float(h2)), __float2half_rn(v.w - __half2float(h3)));
    }
}

// ---- GEMM1 (128x128, 2-term split), DOUBLE-BUFFERED smem, fused epilogue ---
#define BM 128
#define BN 128
#define BK 32
#define LDA 40
#define LDB 136
#define AS_BYTES (BM * LDA * 2)                      // 10240
#define BS_BYTES (BK * LDB * 2)                      // 8704
#define STAGE_BYTES (AS_BYTES + 2 * BS_BYTES)        // 27648
#define GEMM1_DYN (2 * STAGE_BYTES)                  // 55296

__global__ void __launch_bounds__(256) k_gemm1_mma(const float* __restrict__ a_heads) {
    extern __shared__ char dyn[];
    __shared__ float sred[128][2][2][2];   // [row][head-local][p1/p2][wn parity]
    int tid = threadIdx.x;
    int wid = tid >> 5, lane = tid & 31;
    int wm = wid & 1, wn = wid >> 1;          // warp tile: 64x32
    int row0 = blockIdx.y * BM, col0 = blockIdx.x * BN;

    int arow = tid >> 1, acol = (tid & 1) * 16;   // 16 halves of A per thread
    int bkrow = tid >> 3, bn = (tid & 7) * 16;    // 16 halves of B per thread
    const __half* aph = g_Ahi + (row0 + arow) * FIN + acol;
    const __half* bph = g_Whi + bkrow * 512 + col0 + bn;
    const __half* bpl = g_Wlo + bkrow * 512 + col0 + bn;

    uint4 rah[2], rbh[2], rbl[2];
    rah[0] = *(const uint4*)(aph);     rah[1] = *(const uint4*)(aph + 8);
    rbh[0] = *(const uint4*)(bph);     rbh[1] = *(const uint4*)(bph + 8);
    rbl[0] = *(const uint4*)(bpl);     rbl[1] = *(const uint4*)(bpl + 8);

    float acc[4][4][4];
    #pragma unroll
    for (int mi = 0; mi < 4; mi++)
        #pragma unroll
        for (int ni = 0; ni < 4; ni++)
            #pragma unroll
            for (int q = 0; q < 4; q++) acc[mi][ni][q] = 0.f;

    // store tile 0 into stage 0
    {
        char* st = dyn;
        *(uint4*)(st + (arow * LDA + acol) * 2) = rah[0];
        *(uint4*)(st + (arow * LDA + acol + 8) * 2) = rah[1];
        *(uint4*)(st + AS_BYTES + (bkrow * LDB + bn) * 2) = rbh[0];
        *(uint4*)(st + AS_BYTES + (bkrow * LDB + bn + 8) * 2) = rbh[1];
        *(uint4*)(st + AS_BYTES + BS_BYTES + (bkrow * LDB + bn) * 2) = rbl[0];
        *(uint4*)(st + AS_BYTES + BS_BYTES + (bkrow * LDB + bn + 8) * 2) = rbl[1];
    }
    __syncthreads();

    int buf = 0;
    for (int k0 = 0; k0 < FIN; k0 += BK) {
        bool hasNext = (k0 + BK < FIN);
        if (hasNext) {
            rah[0] = *(const uint4*)(aph + k0 + BK);
            rah[1] = *(const uint4*)(aph + k0 + BK + 8);
            rbh[0] = *(const uint4*)(bph + (k0 + BK) * 512);
            rbh[1] = *(const uint4*)(bph + (k0 + BK) * 512 + 8);
            rbl[0] = *(const uint4*)(bpl + (k0 + BK) * 512);
            rbl[1] = *(const uint4*)(bpl + (k0 + BK) * 512 + 8);
        }
        const char* cs = dyn + buf * STAGE_BYTES;
        const __half(*As)[LDA]   = (const __half(*)[LDA])cs;
        const __half(*Bs_hi)[LDB] = (const __half(*)[LDB])(cs + AS_BYTES);
        const __half(*Bs_lo)[LDB] = (const __half(*)[LDB])(cs + AS_BYTES + BS_BYTES);
        #pragma unroll
        for (int ks = 0; ks < BK; ks += 16) {
            unsigned af[4][4], bfh[4][2], bfl[4][2];
            #pragma unroll
            for (int mi = 0; mi < 4; mi++) {
                int r = wm * 64 + mi * 16 + (lane & 15);
                int c = ks + (lane >> 4) * 8;
                ldm_x4(af[mi], &As[r][c]);
            }
            #pragma unroll
            for (int ni = 0; ni < 4; ni++) {
                int kr = ks + (lane & 15);
                int nc = wn * 32 + ni * 8;
                ldm_x2t(bfh[ni], &Bs_hi[kr][nc]);
                ldm_x2t(bfl[ni], &Bs_lo[kr][nc]);
            }
            #pragma unroll
            for (int mi = 0; mi < 4; mi++)
                #pragma unroll
                for (int ni = 0; ni < 4; ni++) {
                    mma16816(acc[mi][ni], af[mi], bfh[ni]);
                    mma16816(acc[mi][ni], af[mi], bfl[ni]);
                }
        }
        if (hasNext) {
            char* st = dyn + (buf ^ 1) * STAGE_BYTES;
            *(uint4*)(st + (arow * LDA + acol) * 2) = rah[0];
            *(uint4*)(st + (arow * LDA + acol + 8) * 2) = rah[1];
            *(uint4*)(st + AS_BYTES + (bkrow * LDB + bn) * 2) = rbh[0];
            *(uint4*)(st + AS_BYTES + (bkrow * LDB + bn + 8) * 2) = rbh[1];
            *(uint4*)(st + AS_BYTES + BS_BYTES + (bkrow * LDB + bn) * 2) = rbl[0];
            *(uint4*)(st + AS_BYTES + BS_BYTES + (bkrow * LDB + bn + 8) * 2) = rbl[1];
            __syncthreads();
            buf ^= 1;
        }
    }
    // h1h stores — HEAD-MAJOR: g_h1h[head][node][64]
    #pragma unroll
    for (int mi = 0; mi < 4; mi++)
        #pragma unroll
        for (int ni = 0; ni < 4; ni++) {
            int r = row0 + wm * 64 + mi * 16 + (lane >> 2);
            int c = col0 + wn * 32 + ni * 8 + (lane & 3) * 2;
            int head = c >> 6, cl = c & 63;
            __half* base = g_h1h + ((size_t)head * Nn) * HID + cl;
            *(__half2*)(base + r * HID) =
                __floats2half2_rn(acc[mi][ni][0], acc[mi][ni][1]);
            *(__half2*)(base + (r + 8) * HID) =
                __floats2half2_rn(acc[mi][ni][2], acc[mi][ni][3]);
        }
    // fused per-node score epilogue
    {
        int hl = wn >> 1;
        int par = wn & 1;
        const float* av = a_heads + (2 * blockIdx.x + hl) * 128;
        float a1v[8], a2v[8];
        #pragma unroll
        for (int ni = 0; ni < 4; ni++) {
            int cl = par * 32 + ni * 8 + (lane & 3) * 2;  // head-local col (0..63)
            a1v[2 * ni] = av[cl];       a1v[2 * ni + 1] = av[cl + 1];
            a2v[2 * ni] = av[64 + cl];  a2v[2 * ni + 1] = av[65 + cl];
        }
        #pragma unroll
        for (int mi = 0; mi < 4; mi++) {
            float p1a = 0.f, p2a = 0.f, p1b = 0.f, p2b = 0.f;
            #pragma unroll
            for (int ni = 0; ni < 4; ni++) {
                p1a += acc[mi][ni][0] * a1v[2 * ni] + acc[mi][ni][1] * a1v[2 * ni + 1];
                p2a += acc[mi][ni][0] * a2v[2 * ni] + acc[mi][ni][1] * a2v[2 * ni + 1];
                p1b += acc[mi][ni][2] * a1v[2 * ni] + acc[mi][ni][3] * a1v[2 * ni + 1];
                p2b += acc[mi][ni][2] * a2v[2 * ni] + acc[mi][ni][3] * a2v[2 * ni + 1];
            }
            #pragma unroll
            for (int o = 1; o <= 2; o <<= 1) {
                p1a += __shfl_xor_sync(0xffffffffu, p1a, o);
                p2a += __shfl_xor_sync(0xffffffffu, p2a, o);
                p1b += __shfl_xor_sync(0xffffffffu, p1b, o);
                p2b += __shfl_xor_sync(0xffffffffu, p2b, o);
            }
            if ((lane & 3) == 0) {
                int r = wm * 64 + mi * 16 + (lane >> 2);
                sred[r][hl][0][par] = p1a;
                sred[r][hl][1][par] = p2a;
                sred[r + 8][hl][0][par] = p1b;
                sred[r + 8][hl][1][par] = p2b;
            }
        }
        __syncthreads();
        for (int o = tid; o < 512; o += 256) {
            int r = o & 127, hh = (o >> 7) & 1, p = (o >> 8) & 1;
            float val = sred[r][hh][p][0] + sred[r][hh][p][1];
            float* dst = p ? g_s2 : g_s1;
            dst[(2 * blockIdx.x + hh) * Nn + row0 + r] = val;
        }
    }
}

// ------- layer-1 aggregation: 2 warps per (node, head), CONTIGUOUS halves ---
// grid (Nn/4, NH), block 256 = 4 pairs.
__global__ void __launch_bounds__(256) k_agg1(const float* __restrict__ b_heads) {
    __shared__ float wbuf[4][136];
    __shared__ int   cbuf[4][136];
    __shared__ float redm[4][2];
    __shared__ float reds[4][2];
    __shared__ float acc2[4][32][2];   // sub==1 partials
    int w = threadIdx.x >> 5, lane = threadIdx.x & 31;
    int pair = w >> 1, sub = w & 1;
    int i = blockIdx.x * 4 + pair;
    int h = blockIdx.y;
    int p0 = g_rowptr[i], p1 = g_rowptr[i + 1];
    int deg = p1 - p0;
    bool small = (deg <= 128);
    int ha = (deg + 1) >> 1;          // first-half size
    int jb = sub ? ha : 0;
    int je = sub ? deg : ha;
    const __half2* hb = ((const __half2*)g_h1h) + (size_t)h * Nn * 32 + lane;
    float s1i = g_s1[h * Nn + i];
    const float* s2p = g_s2 + h * Nn;

    // pass 1: scores + max (contiguous, coalesced)
    float m = -1e30f;
    for (int j = jb + lane; j < je; j += 32) {
        int t = g_col[p0 + j];
        float e = s1i + s2p[t];
        e = e > 0.f ? e : LALPHA * e;
        if (small) { cbuf[pair][j] = t; wbuf[pair][j] = e; }
        m = fmaxf(m, e);
    }
    m = wredmax(m);
    if (lane == 0) redm[pair][sub] = m;
    __syncthreads();
    m = fmaxf(redm[pair][0], redm[pair][1]);

    // pass 2: exp + sum
    float ss = 0.f;
    if (small) {
        for (int j = jb + lane; j < je; j += 32) {
            float wv = expf(wbuf[pair][j] - m);
            wbuf[pair][j] = wv;
            ss += wv;
        }
    } else {
        for (int j = jb + lane; j < je; j += 32) {
            int t = g_col[p0 + j];
            float e = s1i + s2p[t];
            e = e > 0.f ? e : LALPHA * e;
            ss += expf(e - m);
        }
    }
    ss = wredsum(ss);
    if (lane == 0) reds[pair][sub] = ss;
    __syncthreads();
    float sums = reds[pair][0] + reds[pair][1];
    float inv = (sums > 0.f) ? 1.f / sums : 0.f;

    // apply: warp sub walks its contiguous half serially; lanes over dims
    float a0 = 0.f, a1 = 0.f;
    if (small) {
        #pragma unroll 4
        for (int j = jb; j < je; j++) {
            int t = cbuf[pair][j];
            float wv = wbuf[pair][j];
            float2 v = __half22float2(hb[t * 32]);
            a0 = fmaf(wv, v.x, a0);
            a1 = fmaf(wv, v.y, a1);
        }
    } else {
        for (int j = jb; j < je; j++) {
            int t = g_col[p0 + j];
            float e = s1i + s2p[t];
            e = e > 0.f ? e : LALPHA * e;
            float wv = expf(e - m);
            float2 v = __half22float2(hb[t * 32]);
            a0 = fmaf(wv, v.x, a0);
            a1 = fmaf(wv, v.y, a1);
        }
    }
    if (sub == 1) { acc2[pair][lane][0] = a0; acc2[pair][lane][1] = a1; }
    __syncthreads();
    if (sub == 0) {
        float o0 = (a0 + acc2[pair][lane][0]) * inv;
        float o1 = (a1 + acc2[pair][lane][1]) * inv;
        int c0 = h * HID + 2 * lane;
        o0 += b_heads[c0];
        o1 += b_heads[c0 + 1];
        o0 = o0 > 0.f ? o0 : expm1f(o0);   // elu
        o1 = o1 > 0.f ? o1 : expm1f(o1);
        *(__half2*)(g_xh + i * 512 + c0) = __floats2half2_rn(o0, o1);
    }
}

// ------ GEMM2: smem-staged x (16 rows) + fp16 W, fused layer-2 scores ------
#define LDX 520
__global__ void __launch_bounds__(256) k_gemm2(const float* __restrict__ Wout,
                                               const float* __restrict__ a_out) {
    __shared__ __half WsT[NC][LDX];   // transposed, padded (halves)
    __shared__ __half xs[16][LDX];
    int tid = threadIdx.x;
    for (int j = tid; j < 512 * NC; j += 256)
        WsT[j & 15][j >> 4] = __float2half_rn(Wout[j]);
    int row0 = blockIdx.x * 16;
    const uint4* xsrc = (const uint4*)(g_xh + row0 * 512);
    for (int j = tid; j < 16 * 64; j += 256) {       // 64 uint4 per row
        int r = j >> 6, off = j & 63;
        ((uint4*)&xs[r][0])[off] = xsrc[r * 64 + off];
    }
    __syncthreads();
    int col = tid & 15, rs = tid >> 4;
    int row = row0 + rs;
    const __half2* xp = (const __half2*)&xs[rs][0];
    const __half2* wp = (const __half2*)&WsT[col][0];
    float a0 = 0.f, a1 = 0.f, a2 = 0.f, a3 = 0.f;
    #pragma unroll 8
    for (int k = 0; k < 256; k += 2) {
        float2 x0 = __half22float2(xp[k]);
        float2 w0 = __half22float2(wp[k]);
        float2 x1 = __half22float2(xp[k + 1]);
        float2 w1 = __half22float2(wp[k + 1]);
        a0 = fmaf(x0.x, w0.x, a0);
        a1 = fmaf(x0.y, w0.y, a1);
        a2 = fmaf(x1.x, w1.x, a2);
        a3 = fmaf(x1.y, w1.y, a3);
    }
    float v = (a0 + a1) + (a2 + a3);
    g_h2h[row * NC + col] = __float2half_rn(v);
    // fused scores2
    float q1 = v * a_out[col];
    float q2 = v * a_out[16 + col];
    #pragma unroll
    for (int o = 8; o; o >>= 1) {
        q1 += __shfl_xor_sync(0xffffffffu, q1, o);
        q2 += __shfl_xor_sync(0xffffffffu, q2, o);
    }
    if (col == 0) { g_t1[row] = q1; g_t2[row] = q2; }
}

// ---------------- layer-2 aggregation + log_softmax ----------------
__global__ void __launch_bounds__(256) k_agg2(const float* __restrict__ b_out,
                                              float* __restrict__ out) {
    __shared__ float wbuf[8][132];
    __shared__ int   cbuf[8][132];
    int wid = threadIdx.x >> 5, lane = threadIdx.x & 31;
    int grp = lane >> 4, l16 = lane & 15;
    int i = blockIdx.x * 8 + wid;
    int p0 = g_rowptr[i], p1 = g_rowptr[i + 1];
    int deg = p1 - p0;
    float logit = 0.f;
    if (deg > 0 && deg <= 128) {
        float t1i = g_t1[i];
        float m = -1e30f;
        for (int j = lane; j < deg; j += 32) {
            int t = g_col[p0 + j];
            cbuf[wid][j] = t;
            float e = t1i + g_t2[t];
            e = e > 0.f ? e : LALPHA * e;
            wbuf[wid][j] = e;
            m = fmaxf(m, e);
        }
        m = wredmax(m);
        float ss = 0.f;
        for (int j = lane; j < deg; j += 32) {
            float w = expf(wbuf[wid][j] - m);
            wbuf[wid][j] = w;
            ss += w;
        }
        ss = wredsum(ss);
        __syncwarp();
        float inv = 1.f / ss;
        float acc = 0.f;
        #pragma unroll 4
        for (int j = grp; j < deg; j += 2) {
            int t = cbuf[wid][j];
            float w = wbuf[wid][j];
            acc = fmaf(w, __half2float(g_h2h[t * NC + l16]), acc);
        }
        acc += __shfl_xor_sync(0xffffffffu, acc, 16);
        if (lane < 16) logit = acc * inv + b_out[lane];
    } else if (deg > 128) {
        float t1i = g_t1[i];
        float m = -1e30f;
        for (int p = p0 + lane; p < p1; p += 32) {
            float e = t1i + g_t2[g_col[p]];
            e = e > 0.f ? e : LALPHA * e;
            m = fmaxf(m, e);
        }
        m = wredmax(m);
        float ss = 0.f;
        for (int p = p0 + lane; p < p1; p += 32) {
            float e = t1i + g_t2[g_col[p]];
            e = e > 0.f ? e : LALPHA * e;
            ss += expf(e - m);
        }
        ss = wredsum(ss);
        float inv = 1.f / ss;
        float acc = 0.f;
        for (int p = p0 + grp; p < p1; p += 2) {
            int t = g_col[p];
            float e = t1i + g_t2[t];
            e = e > 0.f ? e : LALPHA * e;
            float w = expf(e - m) * inv;
            acc = fmaf(w, __half2float(g_h2h[t * NC + l16]), acc);
        }
        acc += __shfl_xor_sync(0xffffffffu, acc, 16);
        if (lane < 16) logit = acc + b_out[lane];
    } else {
        if (lane < 16) logit = b_out[lane];   // deg==0: unreachable on this dataset
    }
    // log_softmax over 16 classes
    float lm = (lane < 16) ? logit : -1e30f;
    #pragma unroll
    for (int o = 8; o; o >>= 1) lm = fmaxf(lm, __shfl_xor_sync(0xffffffffu, lm, o));
    float es = (lane < 16) ? expf(logit - lm) : 0.f;
    #pragma unroll
    for (int o = 8; o; o >>= 1) es += __shfl_xor_sync(0xffffffffu, es, o);
    if (lane < 16) out[i * NC + lane] = logit - lm - logf(es);
}

// -------- side stream + one-time attribute setup (host resources only) -----
struct SideStream {
    cudaStream_t s2;
    cudaEvent_t eFork, eJoin;
    SideStream() {
        cudaStreamCreateWithFlags(&s2, cudaStreamNonBlocking);
        cudaEventCreateWithFlags(&eFork, cudaEventDisableTiming);
        cudaEventCreateWithFlags(&eJoin, cudaEventDisableTiming);
        cudaFuncSetAttribute(k_gemm1_mma,
            cudaFuncAttributeMaxDynamicSharedMemorySize, GEMM1_DYN);
    }
};
static SideStream g_ss;

// ---------------- launch ----------------
extern "C" void kernel_launch(void* const* d_in, const int* in_sizes, int n_in,
                              void* d_out, int out_size) {
    const float* features    = (const float*)d_in[0];
    const int* el            = (const int*)d_in[1];
    const float* W_heads     = (const float*)d_in[2];
    const float* a_heads     = (const float*)d_in[3];
    const float* b_heads     = (const float*)d_in[4];
    const float* W_out       = (const float*)d_in[5];
    const float* a_out       = (const float*)d_in[6];
    const float* b_out       = (const float*)d_in[7];
    float* out = (float*)d_out;

    // fork: graph-build chain on side stream
    cudaEventRecord(g_ss.eFork, 0);
    cudaStreamWaitEvent(g_ss.s2, g_ss.eFork, 0);
    k_clear_graph<<<(Nn * Nn / 128 + 255) / 256, 256, 0, g_ss.s2>>>();
    k_dedup<<<Ee / 512, 256, 0, g_ss.s2>>>(el);
    k_scan<<<1, 1024, 0, g_ss.s2>>>();
    k_scatter<<<Ee / 512, 256, 0, g_ss.s2>>>(el);
    cudaEventRecord(g_ss.eJoin, g_ss.s2);

    // main chain: compute
    k_tohalf<<<(Nn * FIN / 4 + FIN * 512 / 4 + 255) / 256, 256>>>(features, W_heads);
    k_gemm1_mma<<<dim3(4, 32), 256, GEMM1_DYN>>>(a_heads);

    // join, then the dependent tail
    cudaStreamWaitEvent(0, g_ss.eJoin, 0);
    k_agg1<<<dim3(Nn / 4, NH), 256>>>(b_heads);
    k_gemm2<<<Nn / 16, 256>>>(W_out, a_out);
    k_agg2<<<Nn / 8, 256>>>(b_out, out);
}